// round 1
// baseline (speedup 1.0000x reference)
#include <cuda_runtime.h>
#include <math.h>

#define BB 4
#define LL 2048
#define CIN 64
#define COUTN 64
#define DM 1024
#define NH 16
#define DH 64
#define FF 4096
#define MM (BB*LL)

#define ACT_NONE 0
#define ACT_RELU 1
#define ACT_SIG  2

// ---------------- scratch (device globals; no cudaMalloc allowed) ----------------
__device__ float g_in192[(size_t)MM*192];
__device__ float g_h [(size_t)MM*DM];
__device__ float g_h2[(size_t)MM*DM];
__device__ float g_q [(size_t)MM*DM];
__device__ float g_k [(size_t)MM*DM];
__device__ float g_v [(size_t)MM*DM];
__device__ float g_a [(size_t)MM*DM];
__device__ float g_t [(size_t)MM*FF];
__device__ float g_nr [BB*NH*LL];
__device__ float g_nc [BB*NH*LL];
__device__ float g_nrr[BB*NH*LL];
__device__ float g_sw [BB*NH*LL];
__device__ float g_part[BB*16*DM];
__device__ float g_gate[BB*DM];

// ---------------- generic fp32 GEMM: C[m,n] = sum_k A[m,k]*W[n,k] (+bias)(+res)(act) ----
__global__ __launch_bounds__(256) void gemm_kernel(
    const float* __restrict__ A, const float* __restrict__ W,
    const float* __restrict__ bias, const float* __restrict__ res,
    float* __restrict__ C, int Mm, int Nn, int Kk, int act)
{
    __shared__ float As[16][132];
    __shared__ float Ws[16][132];
    const int bm = blockIdx.y * 128, bn = blockIdx.x * 128;
    const int tid = threadIdx.x;
    const int tr = tid >> 4, tc = tid & 15;

    float acc[8][8];
#pragma unroll
    for (int i = 0; i < 8; i++)
#pragma unroll
        for (int j = 0; j < 8; j++) acc[i][j] = 0.f;

    for (int k0 = 0; k0 < Kk; k0 += 16) {
#pragma unroll
        for (int i = 0; i < 2; i++) {
            int idx = tid + i * 256;      // 0..511 float4 slots
            int row = idx >> 2;           // 0..127
            int k4  = (idx & 3) << 2;     // 0,4,8,12
            float4 va = *(const float4*)(A + (size_t)(bm + row) * Kk + k0 + k4);
            As[k4+0][row] = va.x; As[k4+1][row] = va.y;
            As[k4+2][row] = va.z; As[k4+3][row] = va.w;
            float4 vw = *(const float4*)(W + (size_t)(bn + row) * Kk + k0 + k4);
            Ws[k4+0][row] = vw.x; Ws[k4+1][row] = vw.y;
            Ws[k4+2][row] = vw.z; Ws[k4+3][row] = vw.w;
        }
        __syncthreads();
#pragma unroll
        for (int k = 0; k < 16; k++) {
            float ar[8], wr[8];
            *(float4*)&ar[0] = *(const float4*)&As[k][tr*8];
            *(float4*)&ar[4] = *(const float4*)&As[k][tr*8+4];
            *(float4*)&wr[0] = *(const float4*)&Ws[k][tc*8];
            *(float4*)&wr[4] = *(const float4*)&Ws[k][tc*8+4];
#pragma unroll
            for (int i = 0; i < 8; i++)
#pragma unroll
                for (int j = 0; j < 8; j++)
                    acc[i][j] = fmaf(ar[i], wr[j], acc[i][j]);
        }
        __syncthreads();
    }
#pragma unroll
    for (int i = 0; i < 8; i++) {
        int m = bm + tr*8 + i;
#pragma unroll
        for (int j = 0; j < 8; j++) {
            int n = bn + tc*8 + j;
            float vv = acc[i][j];
            if (bias) vv += bias[n];
            if (res)  vv += res[(size_t)m * Nn + n];
            if (act == ACT_RELU)     vv = fmaxf(vv, 0.f);
            else if (act == ACT_SIG) vv = 1.f / (1.f + expf(-vv));
            C[(size_t)m * Nn + n] = vv;
        }
    }
}

// ---------------- token embed gather: A'[m, c*3+k] = x[b, (l+k-1)%L, c] ----------------
__global__ void gather192(const float* __restrict__ x, float* __restrict__ a)
{
    int m = blockIdx.x;
    int b = m / LL, l = m % LL;
    int t = threadIdx.x;          // 0..191
    int c = t / 3, kk = t % 3;
    int ll = l + kk - 1;
    ll = (ll + LL) % LL;
    a[(size_t)m * 192 + t] = x[((size_t)b * LL + ll) * CIN + c];
}

// ---------------- layer norm over last dim (1024) ----------------
__global__ __launch_bounds__(256) void ln_kernel(
    const float* __restrict__ x, const float* __restrict__ w,
    const float* __restrict__ b, float* __restrict__ out)
{
    __shared__ float sred[256];
    int m = blockIdx.x, tid = threadIdx.x;
    const float* row = x + (size_t)m * DM;
    float v[4];
    float s = 0.f;
#pragma unroll
    for (int i = 0; i < 4; i++) { v[i] = row[tid + i*256]; s += v[i]; }
    sred[tid] = s; __syncthreads();
    for (int o = 128; o >= 1; o >>= 1) { if (tid < o) sred[tid] += sred[tid + o]; __syncthreads(); }
    float mean = sred[0] * (1.f/1024.f);
    __syncthreads();
    float qv = 0.f;
#pragma unroll
    for (int i = 0; i < 4; i++) { float d = v[i] - mean; qv += d*d; }
    sred[tid] = qv; __syncthreads();
    for (int o = 128; o >= 1; o >>= 1) { if (tid < o) sred[tid] += sred[tid + o]; __syncthreads(); }
    float inv = rsqrtf(sred[0] * (1.f/1024.f) + 1e-5f);
#pragma unroll
    for (int i = 0; i < 4; i++) {
        int c = tid + i*256;
        out[(size_t)m * DM + c] = (v[i] - mean) * inv * w[c] + b[c];
    }
}

// ---------------- flow attention: one block per (b,h) ----------------
__global__ __launch_bounds__(512) void flow_attn(
    const float* __restrict__ q, const float* __restrict__ k,
    const float* __restrict__ v, float* __restrict__ out,
    float* __restrict__ nr, float* __restrict__ nc,
    float* __restrict__ nrr, float* __restrict__ sw)
{
    const int bh = blockIdx.x;
    const int b = bh / NH, h = bh % NH;
    const size_t base = ((size_t)b * LL) * DM + (size_t)h * DH;   // row stride DM
    const int tid = threadIdx.x;
    const float eps = 1e-6f;

    __shared__ float ksum[64], qsum[64], skn[64], sqn[64];
    __shared__ float red[512];
    __shared__ float kv[64][64];
    __shared__ float kt[32][64], vt[32][64], wt[32];

    const int d8 = tid & 63, ch = tid >> 6;   // 8 chunks x 64 dims

    // ---- step 1: ksum, qsum ----
    {
        float aq = 0.f, ak = 0.f;
        for (int l = ch; l < LL; l += 8) {
            size_t off = base + (size_t)l * DM + d8;
            aq += q[off]; ak += k[off];
        }
        red[tid] = aq; __syncthreads();
        for (int s = 4; s >= 1; s >>= 1) { if (ch < s) red[tid] += red[tid + (s<<6)]; __syncthreads(); }
        if (tid < 64) qsum[tid] = red[tid];
        __syncthreads();
        red[tid] = ak; __syncthreads();
        for (int s = 4; s >= 1; s >>= 1) { if (ch < s) red[tid] += red[tid + (s<<6)]; __syncthreads(); }
        if (tid < 64) ksum[tid] = red[tid];
        __syncthreads();
    }

    // ---- step 2: nr[l], nc[s] ----
    for (int l = tid; l < LL; l += 512) {
        const float* qr = q + base + (size_t)l * DM;
        const float* kr = k + base + (size_t)l * DM;
        float dq = 0.f, dk = 0.f;
#pragma unroll
        for (int d = 0; d < 64; d++) {
            dq += (qr[d] + eps) * (ksum[d] + eps);
            dk += (kr[d] + eps) * (qsum[d] + eps);
        }
        nr[bh*LL + l] = 1.f / dq;
        nc[bh*LL + l] = 1.f / dk;
    }
    __syncthreads();

    // ---- step 3: skn = sum_s k*nc ; sqn = sum_l q*nr ----
    {
        float a1 = 0.f, a2 = 0.f;
        for (int l = ch; l < LL; l += 8) {
            size_t off = base + (size_t)l * DM + d8;
            a1 += k[off] * nc[bh*LL + l];
            a2 += q[off] * nr[bh*LL + l];
        }
        red[tid] = a1; __syncthreads();
        for (int s = 4; s >= 1; s >>= 1) { if (ch < s) red[tid] += red[tid + (s<<6)]; __syncthreads(); }
        if (tid < 64) skn[tid] = red[tid];
        __syncthreads();
        red[tid] = a2; __syncthreads();
        for (int s = 4; s >= 1; s >>= 1) { if (ch < s) red[tid] += red[tid + (s<<6)]; __syncthreads(); }
        if (tid < 64) sqn[tid] = red[tid];
        __syncthreads();
    }

    // ---- step 4: ncr (softmax*L), nrr ----
    float lmax = -1e30f;
    for (int l = tid; l < LL; l += 512) {
        const float* kr = k + base + (size_t)l * DM;
        const float* qr = q + base + (size_t)l * DM;
        float dc = 0.f, dr = 0.f;
#pragma unroll
        for (int d = 0; d < 64; d++) {
            dc += (kr[d] + eps) * (sqn[d] + eps);
            dr += (qr[d] + eps) * (skn[d] + eps);
        }
        sw[bh*LL + l] = dc;
        nrr[bh*LL + l] = 1.f / (1.f + expf(-dr));   // L/S == 1
        lmax = fmaxf(lmax, dc);
    }
    red[tid] = lmax; __syncthreads();
    for (int s = 256; s >= 1; s >>= 1) { if (tid < s) red[tid] = fmaxf(red[tid], red[tid + s]); __syncthreads(); }
    float mx = red[0];
    __syncthreads();
    float lsum = 0.f;
    for (int l = tid; l < LL; l += 512) {
        float e = expf(sw[bh*LL + l] - mx);
        sw[bh*LL + l] = e;
        lsum += e;
    }
    red[tid] = lsum; __syncthreads();
    for (int s = 256; s >= 1; s >>= 1) { if (tid < s) red[tid] += red[tid + s]; __syncthreads(); }
    const float wfac = (float)LL / red[0];
    __syncthreads();

    // ---- step 5: kv[d][e] = sum_s k[s,d] * (v[s,e] * w[s]) ----
    {
        float acc[8];
#pragma unroll
        for (int j = 0; j < 8; j++) acc[j] = 0.f;
        const int dd = tid >> 3, e0 = (tid & 7) << 3;
        for (int s0 = 0; s0 < LL; s0 += 32) {
            for (int i = tid; i < 2048; i += 512) {
                int ss = i >> 6, cc = i & 63;
                size_t off = base + (size_t)(s0 + ss) * DM + cc;
                kt[ss][cc] = k[off];
                vt[ss][cc] = v[off];
            }
            if (tid < 32) wt[tid] = sw[bh*LL + s0 + tid] * wfac;
            __syncthreads();
#pragma unroll 4
            for (int ss = 0; ss < 32; ss++) {
                float kw = kt[ss][dd] * wt[ss];
#pragma unroll
                for (int j = 0; j < 8; j++) acc[j] = fmaf(kw, vt[ss][e0 + j], acc[j]);
            }
            __syncthreads();
        }
#pragma unroll
        for (int j = 0; j < 8; j++) kv[dd][e0 + j] = acc[j];
        __syncthreads();
    }

    // ---- step 6: out[l,e] = (q[l,:] . kv[:,e]) * nr[l] * nrr[l] ----
    {
        const int e = tid & 63, l0 = tid >> 6;
        for (int l = l0; l < LL; l += 8) {
            const float* qr = q + base + (size_t)l * DM;
            float a = 0.f;
#pragma unroll
            for (int d = 0; d < 64; d++) a = fmaf(qr[d], kv[d][e], a);
            out[base + (size_t)l * DM + e] = a * nr[bh*LL + l] * nrr[bh*LL + l];
        }
    }
}

// ---------------- channel attention ----------------
__global__ __launch_bounds__(1024) void ca_partial(const float* __restrict__ x, float* __restrict__ part)
{
    int b = blockIdx.x, chk = blockIdx.y, c = threadIdx.x;
    float s = 0.f;
    int l0 = chk * 128;
    for (int l = l0; l < l0 + 128; l++) s += x[((size_t)b * LL + l) * DM + c];
    part[((size_t)b * 16 + chk) * DM + c] = s;
}

__global__ __launch_bounds__(1024) void ca_gate(const float* __restrict__ part,
                                                const float* __restrict__ caw,
                                                float* __restrict__ gate)
{
    __shared__ float m[DM + 4];
    int b = blockIdx.x, c = threadIdx.x;
    float s = 0.f;
    for (int p = 0; p < 16; p++) s += part[((size_t)b * 16 + p) * DM + c];
    m[c + 2] = s * (1.f / (float)LL);
    if (c < 2) m[c] = 0.f;
    if (c >= DM - 2) m[c + 4] = 0.f;
    __syncthreads();
    float g = 0.f;
#pragma unroll
    for (int kk = 0; kk < 5; kk++) g += caw[kk] * m[c + kk];
    gate[(size_t)b * DM + c] = 1.f / (1.f + expf(-g));
}

__global__ __launch_bounds__(1024) void ca_mul(float* __restrict__ x, const float* __restrict__ gate)
{
    int mrow = blockIdx.x;
    int b = mrow / LL;
    int c = threadIdx.x;
    x[(size_t)mrow * DM + c] *= gate[(size_t)b * DM + c];
}

// ---------------- final projection: out[m,n] = h[m,:] . pw[n,:] + pb[n] ----------------
__global__ __launch_bounds__(64) void proj_kernel(const float* __restrict__ hln,
                                                  const float* __restrict__ pw,
                                                  const float* __restrict__ pb,
                                                  float* __restrict__ out)
{
    int m = blockIdx.x, n = threadIdx.x;
    const float* hr = hln + (size_t)m * DM;
    const float* wr = pw + (size_t)n * DM;
    float a = 0.f;
    const float4* h4 = (const float4*)hr;
    const float4* w4 = (const float4*)wr;
#pragma unroll 4
    for (int kk = 0; kk < DM/4; kk++) {
        float4 hv = h4[kk], wv = w4[kk];
        a += hv.x*wv.x + hv.y*wv.y + hv.z*wv.z + hv.w*wv.w;
    }
    out[(size_t)m * COUTN + n] = a + pb[n];
}

// ---------------- host ----------------
extern "C" void kernel_launch(void* const* d_in, const int* in_sizes, int n_in,
                              void* d_out, int out_size)
{
    const float* x    = (const float*)d_in[0];
    const float* tokw = (const float*)d_in[1];
    const float* Wq   = (const float*)d_in[2];
    const float* bq   = (const float*)d_in[3];
    const float* Wk   = (const float*)d_in[4];
    const float* bk   = (const float*)d_in[5];
    const float* Wv   = (const float*)d_in[6];
    const float* bv   = (const float*)d_in[7];
    const float* Wo   = (const float*)d_in[8];
    const float* bo   = (const float*)d_in[9];
    const float* c1w  = (const float*)d_in[10];
    const float* c1b  = (const float*)d_in[11];
    const float* c2w  = (const float*)d_in[12];
    const float* c2b  = (const float*)d_in[13];
    const float* ln1w = (const float*)d_in[14];
    const float* ln1b = (const float*)d_in[15];
    const float* ln2w = (const float*)d_in[16];
    const float* ln2b = (const float*)d_in[17];
    const float* caw  = (const float*)d_in[18];
    const float* lnfw = (const float*)d_in[19];
    const float* lnfb = (const float*)d_in[20];
    const float* pw   = (const float*)d_in[21];
    const float* pb   = (const float*)d_in[22];

    float *p_in192, *p_h, *p_h2, *p_q, *p_k, *p_v, *p_a, *p_t;
    float *p_nr, *p_nc, *p_nrr, *p_sw, *p_part, *p_gate;
    cudaGetSymbolAddress((void**)&p_in192, g_in192);
    cudaGetSymbolAddress((void**)&p_h,  g_h);
    cudaGetSymbolAddress((void**)&p_h2, g_h2);
    cudaGetSymbolAddress((void**)&p_q,  g_q);
    cudaGetSymbolAddress((void**)&p_k,  g_k);
    cudaGetSymbolAddress((void**)&p_v,  g_v);
    cudaGetSymbolAddress((void**)&p_a,  g_a);
    cudaGetSymbolAddress((void**)&p_t,  g_t);
    cudaGetSymbolAddress((void**)&p_nr,  g_nr);
    cudaGetSymbolAddress((void**)&p_nc,  g_nc);
    cudaGetSymbolAddress((void**)&p_nrr, g_nrr);
    cudaGetSymbolAddress((void**)&p_sw,  g_sw);
    cudaGetSymbolAddress((void**)&p_part, g_part);
    cudaGetSymbolAddress((void**)&p_gate, g_gate);

    dim3 gN(DM/128, MM/128);   // N=1024 outputs
    dim3 gF(FF/128, MM/128);   // N=4096 outputs

    // token embedding (circular conv k=3) as gather + GEMM (K=192)
    gather192<<<MM, 192>>>(x, p_in192);
    gemm_kernel<<<gN, 256>>>(p_in192, tokw, nullptr, nullptr, p_h, MM, DM, 192, ACT_NONE);

    for (int rep = 0; rep < 5; rep++) {
        int i = (rep < 4) ? rep : 3;
        const float* wq = Wq + (size_t)i * DM * DM;
        const float* wk = Wk + (size_t)i * DM * DM;
        const float* wv = Wv + (size_t)i * DM * DM;
        const float* wo = Wo + (size_t)i * DM * DM;

        gemm_kernel<<<gN, 256>>>(p_h, wq, bq + i*DM, nullptr, p_q, MM, DM, DM, ACT_SIG);
        gemm_kernel<<<gN, 256>>>(p_h, wk, bk + i*DM, nullptr, p_k, MM, DM, DM, ACT_SIG);
        gemm_kernel<<<gN, 256>>>(p_h, wv, bv + i*DM, nullptr, p_v, MM, DM, DM, ACT_NONE);

        flow_attn<<<BB*NH, 512>>>(p_q, p_k, p_v, p_a, p_nr, p_nc, p_nrr, p_sw);

        // attn out proj + residual -> p_q (scratch), then LN1 -> p_h2
        gemm_kernel<<<gN, 256>>>(p_a, wo, bo + i*DM, p_h, p_q, MM, DM, DM, ACT_NONE);
        ln_kernel<<<MM, 256>>>(p_q, ln1w + i*DM, ln1b + i*DM, p_h2);

        // FFN
        gemm_kernel<<<gF, 256>>>(p_h2, c1w + (size_t)i*FF*DM, c1b + i*FF, nullptr,
                                 p_t, MM, FF, DM, ACT_RELU);
        gemm_kernel<<<gN, 256>>>(p_t, c2w + (size_t)i*DM*FF, c2b + i*DM, p_h2,
                                 p_q, MM, DM, FF, ACT_NONE);
        ln_kernel<<<MM, 256>>>(p_q, ln2w + i*DM, ln2b + i*DM, p_h);

        if (rep < 4) {
            ca_partial<<<dim3(BB, 16), 1024>>>(p_h, p_part);
            ca_gate<<<BB, 1024>>>(p_part, caw + i*5, p_gate);
            ca_mul<<<MM, 1024>>>(p_h, p_gate);
        }
    }

    ln_kernel<<<MM, 256>>>(p_h, lnfw, lnfb, p_h2);
    proj_kernel<<<MM, 64>>>(p_h2, pw, pb, (float*)d_out);
}

// round 2
// speedup vs baseline: 2.2883x; 2.2883x over previous
#include <cuda_runtime.h>
#include <math.h>

#define BB 4
#define LL 2048
#define CIN 64
#define COUTN 64
#define DM 1024
#define NH 16
#define DH 64
#define FF 4096
#define MM (BB*LL)

#define ACT_NONE 0
#define ACT_RELU 1
#define ACT_SIG  2

// ---------------- scratch (device globals; no cudaMalloc allowed) ----------------
__device__ float g_in192[(size_t)MM*192];
__device__ float g_h [(size_t)MM*DM];
__device__ float g_h2[(size_t)MM*DM];
__device__ float g_q [(size_t)MM*DM];
__device__ float g_k [(size_t)MM*DM];
__device__ float g_v [(size_t)MM*DM];
__device__ float g_a [(size_t)MM*DM];
__device__ float g_t [(size_t)MM*FF];
__device__ float g_nr [BB*NH*LL];
__device__ float g_nc [BB*NH*LL];
__device__ float g_nrr[BB*NH*LL];
__device__ float g_sw [BB*NH*LL];
__device__ float g_part[BB*16*DM];
__device__ float g_gate[BB*DM];

__device__ __forceinline__ float to_tf32(float x) {
    float r;
    asm("cvt.rna.tf32.f32 %0, %1;" : "=f"(r) : "f"(x));
    return r;
}

__device__ __forceinline__ void mma_tf32(float* d, const unsigned* a, const unsigned* b) {
    asm volatile(
        "mma.sync.aligned.m16n8k8.row.col.f32.tf32.tf32.f32 "
        "{%0,%1,%2,%3}, {%4,%5,%6,%7}, {%8,%9}, {%0,%1,%2,%3};"
        : "+f"(d[0]), "+f"(d[1]), "+f"(d[2]), "+f"(d[3])
        : "r"(a[0]), "r"(a[1]), "r"(a[2]), "r"(a[3]), "r"(b[0]), "r"(b[1]));
}

// ---------------- tf32 tensor-core GEMM: C[m,n] = sum_k A[m,k]*W[n,k] (+bias)(+res)(act)
// BM=128, BN=128, BK=32, 256 threads = 8 warps (2 x 4), warp tile 64x32
#define GBM 128
#define GBN 128
#define GBK 32
#define SSTR 36   // smem row stride (floats); makes fragment LDS conflict-free

__global__ __launch_bounds__(256) void gemm_tc(
    const float* __restrict__ A, const float* __restrict__ W,
    const float* __restrict__ bias, const float* __restrict__ res,
    float* __restrict__ C, int Mm, int Nn, int Kk, int act)
{
    __shared__ float As[GBM * SSTR];
    __shared__ float Bs[GBN * SSTR];

    const int bm = blockIdx.y * GBM, bn = blockIdx.x * GBN;
    const int tid = threadIdx.x;
    const int warp = tid >> 5, lane = tid & 31;
    const int gid = lane >> 2, tig = lane & 3;
    const int wm = (warp & 1) * 64;      // warp m offset within block
    const int wn = (warp >> 1) * 32;     // warp n offset within block

    float acc[4][4][4];   // [mi][ni][reg]
#pragma unroll
    for (int mi = 0; mi < 4; mi++)
#pragma unroll
        for (int ni = 0; ni < 4; ni++)
#pragma unroll
            for (int r = 0; r < 4; r++) acc[mi][ni][r] = 0.f;

    // per-thread staging for global->smem (4 float4 for A, 4 for B)
    float4 ra[4], rb[4];
    const int T = Kk / GBK;

    // indices for the 4 staged float4s: idx = tid + i*256 ; row = idx>>3, kq = idx&7
    int rowi[4], kqi[4];
#pragma unroll
    for (int i = 0; i < 4; i++) {
        int idx = tid + i * 256;
        rowi[i] = idx >> 3;
        kqi[i]  = idx & 7;
    }

    // prefetch tile 0
#pragma unroll
    for (int i = 0; i < 4; i++) {
        ra[i] = *(const float4*)(A + (size_t)(bm + rowi[i]) * Kk + kqi[i] * 4);
        rb[i] = *(const float4*)(W + (size_t)(bn + rowi[i]) * Kk + kqi[i] * 4);
    }

    for (int t = 0; t < T; t++) {
        // store staged tile to smem (tf32-rounded)
#pragma unroll
        for (int i = 0; i < 4; i++) {
            float4 va = ra[i], vb = rb[i];
            va.x = to_tf32(va.x); va.y = to_tf32(va.y); va.z = to_tf32(va.z); va.w = to_tf32(va.w);
            vb.x = to_tf32(vb.x); vb.y = to_tf32(vb.y); vb.z = to_tf32(vb.z); vb.w = to_tf32(vb.w);
            *(float4*)(As + rowi[i] * SSTR + kqi[i] * 4) = va;
            *(float4*)(Bs + rowi[i] * SSTR + kqi[i] * 4) = vb;
        }
        __syncthreads();

        // prefetch next tile (overlaps with MMA work below)
        if (t + 1 < T) {
            int k0 = (t + 1) * GBK;
#pragma unroll
            for (int i = 0; i < 4; i++) {
                ra[i] = *(const float4*)(A + (size_t)(bm + rowi[i]) * Kk + k0 + kqi[i] * 4);
                rb[i] = *(const float4*)(W + (size_t)(bn + rowi[i]) * Kk + k0 + kqi[i] * 4);
            }
        }

        // compute: 4 k-steps of 8
#pragma unroll
        for (int kk = 0; kk < GBK; kk += 8) {
            unsigned af[4][4], bf[4][2];
#pragma unroll
            for (int mi = 0; mi < 4; mi++) {
                int r0 = wm + mi * 16 + gid;
                af[mi][0] = __float_as_uint(As[(r0    ) * SSTR + kk + tig    ]);
                af[mi][1] = __float_as_uint(As[(r0 + 8) * SSTR + kk + tig    ]);
                af[mi][2] = __float_as_uint(As[(r0    ) * SSTR + kk + tig + 4]);
                af[mi][3] = __float_as_uint(As[(r0 + 8) * SSTR + kk + tig + 4]);
            }
#pragma unroll
            for (int ni = 0; ni < 4; ni++) {
                int c0 = wn + ni * 8 + gid;
                bf[ni][0] = __float_as_uint(Bs[c0 * SSTR + kk + tig    ]);
                bf[ni][1] = __float_as_uint(Bs[c0 * SSTR + kk + tig + 4]);
            }
#pragma unroll
            for (int mi = 0; mi < 4; mi++)
#pragma unroll
                for (int ni = 0; ni < 4; ni++)
                    mma_tf32(acc[mi][ni], af[mi], bf[ni]);
        }
        __syncthreads();
    }

    // epilogue
#pragma unroll
    for (int mi = 0; mi < 4; mi++) {
#pragma unroll
        for (int ni = 0; ni < 4; ni++) {
            int row = bm + wm + mi * 16 + gid;
            int col = bn + wn + ni * 8 + 2 * tig;
            float b0 = 0.f, b1 = 0.f;
            if (bias) { b0 = bias[col]; b1 = bias[col + 1]; }
#pragma unroll
            for (int half = 0; half < 2; half++) {
                int r = row + half * 8;
                float v0 = acc[mi][ni][half * 2 + 0] + b0;
                float v1 = acc[mi][ni][half * 2 + 1] + b1;
                if (res) {
                    v0 += res[(size_t)r * Nn + col];
                    v1 += res[(size_t)r * Nn + col + 1];
                }
                if (act == ACT_RELU) { v0 = fmaxf(v0, 0.f); v1 = fmaxf(v1, 0.f); }
                else if (act == ACT_SIG) {
                    v0 = 1.f / (1.f + expf(-v0));
                    v1 = 1.f / (1.f + expf(-v1));
                }
                float2 o = make_float2(v0, v1);
                *(float2*)(C + (size_t)r * Nn + col) = o;
            }
        }
    }
}

// ---------------- token embed gather: A'[m, c*3+k] = x[b, (l+k-1)%L, c] ----------------
__global__ void gather192(const float* __restrict__ x, float* __restrict__ a)
{
    int m = blockIdx.x;
    int b = m / LL, l = m % LL;
    int t = threadIdx.x;          // 0..191
    int c = t / 3, kk = t % 3;
    int ll = l + kk - 1;
    ll = (ll + LL) % LL;
    a[(size_t)m * 192 + t] = x[((size_t)b * LL + ll) * CIN + c];
}

// ---------------- layer norm over last dim (1024) ----------------
__global__ __launch_bounds__(256) void ln_kernel(
    const float* __restrict__ x, const float* __restrict__ w,
    const float* __restrict__ b, float* __restrict__ out)
{
    __shared__ float sred[256];
    int m = blockIdx.x, tid = threadIdx.x;
    const float* row = x + (size_t)m * DM;
    float v[4];
    float s = 0.f;
#pragma unroll
    for (int i = 0; i < 4; i++) { v[i] = row[tid + i*256]; s += v[i]; }
    sred[tid] = s; __syncthreads();
    for (int o = 128; o >= 1; o >>= 1) { if (tid < o) sred[tid] += sred[tid + o]; __syncthreads(); }
    float mean = sred[0] * (1.f/1024.f);
    __syncthreads();
    float qv = 0.f;
#pragma unroll
    for (int i = 0; i < 4; i++) { float d = v[i] - mean; qv += d*d; }
    sred[tid] = qv; __syncthreads();
    for (int o = 128; o >= 1; o >>= 1) { if (tid < o) sred[tid] += sred[tid + o]; __syncthreads(); }
    float inv = rsqrtf(sred[0] * (1.f/1024.f) + 1e-5f);
#pragma unroll
    for (int i = 0; i < 4; i++) {
        int c = tid + i*256;
        out[(size_t)m * DM + c] = (v[i] - mean) * inv * w[c] + b[c];
    }
}

// ---------------- flow attention: one block per (b,h) ----------------
__global__ __launch_bounds__(512) void flow_attn(
    const float* __restrict__ q, const float* __restrict__ k,
    const float* __restrict__ v, float* __restrict__ out,
    float* __restrict__ nr, float* __restrict__ nc,
    float* __restrict__ nrr, float* __restrict__ sw)
{
    const int bh = blockIdx.x;
    const int b = bh / NH, h = bh % NH;
    const size_t base = ((size_t)b * LL) * DM + (size_t)h * DH;   // row stride DM
    const int tid = threadIdx.x;
    const float eps = 1e-6f;

    __shared__ float ksum[64], qsum[64], skn[64], sqn[64];
    __shared__ float red[512];
    __shared__ float kv[64][64];
    __shared__ float kt[32][64], vt[32][64], wt[32];

    const int d8 = tid & 63, ch = tid >> 6;   // 8 chunks x 64 dims

    // ---- step 1: ksum, qsum ----
    {
        float aq = 0.f, ak = 0.f;
        for (int l = ch; l < LL; l += 8) {
            size_t off = base + (size_t)l * DM + d8;
            aq += q[off]; ak += k[off];
        }
        red[tid] = aq; __syncthreads();
        for (int s = 4; s >= 1; s >>= 1) { if (ch < s) red[tid] += red[tid + (s<<6)]; __syncthreads(); }
        if (tid < 64) qsum[tid] = red[tid];
        __syncthreads();
        red[tid] = ak; __syncthreads();
        for (int s = 4; s >= 1; s >>= 1) { if (ch < s) red[tid] += red[tid + (s<<6)]; __syncthreads(); }
        if (tid < 64) ksum[tid] = red[tid];
        __syncthreads();
    }

    // ---- step 2: nr[l], nc[s] ----
    for (int l = tid; l < LL; l += 512) {
        const float* qr = q + base + (size_t)l * DM;
        const float* kr = k + base + (size_t)l * DM;
        float dq = 0.f, dk = 0.f;
#pragma unroll
        for (int d = 0; d < 64; d++) {
            dq += (qr[d] + eps) * (ksum[d] + eps);
            dk += (kr[d] + eps) * (qsum[d] + eps);
        }
        nr[bh*LL + l] = 1.f / dq;
        nc[bh*LL + l] = 1.f / dk;
    }
    __syncthreads();

    // ---- step 3: skn = sum_s k*nc ; sqn = sum_l q*nr ----
    {
        float a1 = 0.f, a2 = 0.f;
        for (int l = ch; l < LL; l += 8) {
            size_t off = base + (size_t)l * DM + d8;
            a1 += k[off] * nc[bh*LL + l];
            a2 += q[off] * nr[bh*LL + l];
        }
        red[tid] = a1; __syncthreads();
        for (int s = 4; s >= 1; s >>= 1) { if (ch < s) red[tid] += red[tid + (s<<6)]; __syncthreads(); }
        if (tid < 64) skn[tid] = red[tid];
        __syncthreads();
        red[tid] = a2; __syncthreads();
        for (int s = 4; s >= 1; s >>= 1) { if (ch < s) red[tid] += red[tid + (s<<6)]; __syncthreads(); }
        if (tid < 64) sqn[tid] = red[tid];
        __syncthreads();
    }

    // ---- step 4: ncr (softmax*L), nrr ----
    float lmax = -1e30f;
    for (int l = tid; l < LL; l += 512) {
        const float* kr = k + base + (size_t)l * DM;
        const float* qr = q + base + (size_t)l * DM;
        float dc = 0.f, dr = 0.f;
#pragma unroll
        for (int d = 0; d < 64; d++) {
            dc += (kr[d] + eps) * (sqn[d] + eps);
            dr += (qr[d] + eps) * (skn[d] + eps);
        }
        sw[bh*LL + l] = dc;
        nrr[bh*LL + l] = 1.f / (1.f + expf(-dr));   // L/S == 1
        lmax = fmaxf(lmax, dc);
    }
    red[tid] = lmax; __syncthreads();
    for (int s = 256; s >= 1; s >>= 1) { if (tid < s) red[tid] = fmaxf(red[tid], red[tid + s]); __syncthreads(); }
    float mx = red[0];
    __syncthreads();
    float lsum = 0.f;
    for (int l = tid; l < LL; l += 512) {
        float e = expf(sw[bh*LL + l] - mx);
        sw[bh*LL + l] = e;
        lsum += e;
    }
    red[tid] = lsum; __syncthreads();
    for (int s = 256; s >= 1; s >>= 1) { if (tid < s) red[tid] += red[tid + s]; __syncthreads(); }
    const float wfac = (float)LL / red[0];
    __syncthreads();

    // ---- step 5: kv[d][e] = sum_s k[s,d] * (v[s,e] * w[s]) ----
    {
        float acc[8];
#pragma unroll
        for (int j = 0; j < 8; j++) acc[j] = 0.f;
        const int dd = tid >> 3, e0 = (tid & 7) << 3;
        for (int s0 = 0; s0 < LL; s0 += 32) {
            for (int i = tid; i < 2048; i += 512) {
                int ss = i >> 6, cc = i & 63;
                size_t off = base + (size_t)(s0 + ss) * DM + cc;
                kt[ss][cc] = k[off];
                vt[ss][cc] = v[off];
            }
            if (tid < 32) wt[tid] = sw[bh*LL + s0 + tid] * wfac;
            __syncthreads();
#pragma unroll 4
            for (int ss = 0; ss < 32; ss++) {
                float kw = kt[ss][dd] * wt[ss];
#pragma unroll
                for (int j = 0; j < 8; j++) acc[j] = fmaf(kw, vt[ss][e0 + j], acc[j]);
            }
            __syncthreads();
        }
#pragma unroll
        for (int j = 0; j < 8; j++) kv[dd][e0 + j] = acc[j];
        __syncthreads();
    }

    // ---- step 6: out[l,e] = (q[l,:] . kv[:,e]) * nr[l] * nrr[l] ----
    {
        const int e = tid & 63, l0 = tid >> 6;
        for (int l = l0; l < LL; l += 8) {
            const float* qr = q + base + (size_t)l * DM;
            float a = 0.f;
#pragma unroll
            for (int d = 0; d < 64; d++) a = fmaf(qr[d], kv[d][e], a);
            out[base + (size_t)l * DM + e] = a * nr[bh*LL + l] * nrr[bh*LL + l];
        }
    }
}

// ---------------- channel attention ----------------
__global__ __launch_bounds__(1024) void ca_partial(const float* __restrict__ x, float* __restrict__ part)
{
    int b = blockIdx.x, chk = blockIdx.y, c = threadIdx.x;
    float s = 0.f;
    int l0 = chk * 128;
    for (int l = l0; l < l0 + 128; l++) s += x[((size_t)b * LL + l) * DM + c];
    part[((size_t)b * 16 + chk) * DM + c] = s;
}

__global__ __launch_bounds__(1024) void ca_gate(const float* __restrict__ part,
                                                const float* __restrict__ caw,
                                                float* __restrict__ gate)
{
    __shared__ float m[DM + 4];
    int b = blockIdx.x, c = threadIdx.x;
    float s = 0.f;
    for (int p = 0; p < 16; p++) s += part[((size_t)b * 16 + p) * DM + c];
    m[c + 2] = s * (1.f / (float)LL);
    if (c < 2) m[c] = 0.f;
    if (c >= DM - 2) m[c + 4] = 0.f;
    __syncthreads();
    float g = 0.f;
#pragma unroll
    for (int kk = 0; kk < 5; kk++) g += caw[kk] * m[c + kk];
    gate[(size_t)b * DM + c] = 1.f / (1.f + expf(-g));
}

__global__ __launch_bounds__(1024) void ca_mul(float* __restrict__ x, const float* __restrict__ gate)
{
    int mrow = blockIdx.x;
    int b = mrow / LL;
    int c = threadIdx.x;
    x[(size_t)mrow * DM + c] *= gate[(size_t)b * DM + c];
}

// ---------------- final projection: out[m,n] = h[m,:] . pw[n,:] + pb[n] ----------------
__global__ __launch_bounds__(64) void proj_kernel(const float* __restrict__ hln,
                                                  const float* __restrict__ pw,
                                                  const float* __restrict__ pb,
                                                  float* __restrict__ out)
{
    int m = blockIdx.x, n = threadIdx.x;
    const float* hr = hln + (size_t)m * DM;
    const float* wr = pw + (size_t)n * DM;
    float a = 0.f;
    const float4* h4 = (const float4*)hr;
    const float4* w4 = (const float4*)wr;
#pragma unroll 4
    for (int kk = 0; kk < DM/4; kk++) {
        float4 hv = h4[kk], wv = w4[kk];
        a += hv.x*wv.x + hv.y*wv.y + hv.z*wv.z + hv.w*wv.w;
    }
    out[(size_t)m * COUTN + n] = a + pb[n];
}

// ---------------- host ----------------
extern "C" void kernel_launch(void* const* d_in, const int* in_sizes, int n_in,
                              void* d_out, int out_size)
{
    const float* x    = (const float*)d_in[0];
    const float* tokw = (const float*)d_in[1];
    const float* Wq   = (const float*)d_in[2];
    const float* bq   = (const float*)d_in[3];
    const float* Wk   = (const float*)d_in[4];
    const float* bk   = (const float*)d_in[5];
    const float* Wv   = (const float*)d_in[6];
    const float* bv   = (const float*)d_in[7];
    const float* Wo   = (const float*)d_in[8];
    const float* bo   = (const float*)d_in[9];
    const float* c1w  = (const float*)d_in[10];
    const float* c1b  = (const float*)d_in[11];
    const float* c2w  = (const float*)d_in[12];
    const float* c2b  = (const float*)d_in[13];
    const float* ln1w = (const float*)d_in[14];
    const float* ln1b = (const float*)d_in[15];
    const float* ln2w = (const float*)d_in[16];
    const float* ln2b = (const float*)d_in[17];
    const float* caw  = (const float*)d_in[18];
    const float* lnfw = (const float*)d_in[19];
    const float* lnfb = (const float*)d_in[20];
    const float* pw   = (const float*)d_in[21];
    const float* pb   = (const float*)d_in[22];

    float *p_in192, *p_h, *p_h2, *p_q, *p_k, *p_v, *p_a, *p_t;
    float *p_nr, *p_nc, *p_nrr, *p_sw, *p_part, *p_gate;
    cudaGetSymbolAddress((void**)&p_in192, g_in192);
    cudaGetSymbolAddress((void**)&p_h,  g_h);
    cudaGetSymbolAddress((void**)&p_h2, g_h2);
    cudaGetSymbolAddress((void**)&p_q,  g_q);
    cudaGetSymbolAddress((void**)&p_k,  g_k);
    cudaGetSymbolAddress((void**)&p_v,  g_v);
    cudaGetSymbolAddress((void**)&p_a,  g_a);
    cudaGetSymbolAddress((void**)&p_t,  g_t);
    cudaGetSymbolAddress((void**)&p_nr,  g_nr);
    cudaGetSymbolAddress((void**)&p_nc,  g_nc);
    cudaGetSymbolAddress((void**)&p_nrr, g_nrr);
    cudaGetSymbolAddress((void**)&p_sw,  g_sw);
    cudaGetSymbolAddress((void**)&p_part, g_part);
    cudaGetSymbolAddress((void**)&p_gate, g_gate);

    dim3 gN(DM/128, MM/128);   // N=1024 outputs
    dim3 gF(FF/128, MM/128);   // N=4096 outputs

    // token embedding (circular conv k=3) as gather + GEMM (K=192)
    gather192<<<MM, 192>>>(x, p_in192);
    gemm_tc<<<gN, 256>>>(p_in192, tokw, nullptr, nullptr, p_h, MM, DM, 192, ACT_NONE);

    for (int rep = 0; rep < 5; rep++) {
        int i = (rep < 4) ? rep : 3;
        const float* wq = Wq + (size_t)i * DM * DM;
        const float* wk = Wk + (size_t)i * DM * DM;
        const float* wv = Wv + (size_t)i * DM * DM;
        const float* wo = Wo + (size_t)i * DM * DM;

        gemm_tc<<<gN, 256>>>(p_h, wq, bq + i*DM, nullptr, p_q, MM, DM, DM, ACT_SIG);
        gemm_tc<<<gN, 256>>>(p_h, wk, bk + i*DM, nullptr, p_k, MM, DM, DM, ACT_SIG);
        gemm_tc<<<gN, 256>>>(p_h, wv, bv + i*DM, nullptr, p_v, MM, DM, DM, ACT_NONE);

        flow_attn<<<BB*NH, 512>>>(p_q, p_k, p_v, p_a, p_nr, p_nc, p_nrr, p_sw);

        // attn out proj + residual -> p_q (scratch), then LN1 -> p_h2
        gemm_tc<<<gN, 256>>>(p_a, wo, bo + i*DM, p_h, p_q, MM, DM, DM, ACT_NONE);
        ln_kernel<<<MM, 256>>>(p_q, ln1w + i*DM, ln1b + i*DM, p_h2);

        // FFN
        gemm_tc<<<gF, 256>>>(p_h2, c1w + (size_t)i*FF*DM, c1b + i*FF, nullptr,
                             p_t, MM, FF, DM, ACT_RELU);
        gemm_tc<<<gN, 256>>>(p_t, c2w + (size_t)i*DM*FF, c2b + i*DM, p_h2,
                             p_q, MM, DM, FF, ACT_NONE);
        ln_kernel<<<MM, 256>>>(p_q, ln2w + i*DM, ln2b + i*DM, p_h);

        if (rep < 4) {
            ca_partial<<<dim3(BB, 16), 1024>>>(p_h, p_part);
            ca_gate<<<BB, 1024>>>(p_part, caw + i*5, p_gate);
            ca_mul<<<MM, 1024>>>(p_h, p_gate);
        }
    }

    ln_kernel<<<MM, 256>>>(p_h, lnfw, lnfb, p_h2);
    proj_kernel<<<MM, 64>>>(p_h2, pw, pb, (float*)d_out);
}

// round 4
// speedup vs baseline: 2.5782x; 1.1267x over previous
#include <cuda_runtime.h>
#include <math.h>
#include <stdint.h>

#define BB 4
#define LL 2048
#define CIN 64
#define COUTN 64
#define DM 1024
#define NH 16
#define DH 64
#define FF 4096
#define MM (BB*LL)

#define ACT_NONE 0
#define ACT_RELU 1
#define ACT_SIG  2

// ---------------- scratch (device globals; no cudaMalloc allowed) ----------------
__device__ float g_in192[(size_t)MM*192];
__device__ float g_h [(size_t)MM*DM];
__device__ float g_h2[(size_t)MM*DM];
__device__ float g_q [(size_t)MM*DM];
__device__ float g_k [(size_t)MM*DM];
__device__ float g_v [(size_t)MM*DM];
__device__ float g_a [(size_t)MM*DM];
__device__ float g_t [(size_t)MM*FF];
__device__ float g_nr [BB*NH*LL];
__device__ float g_nc [BB*NH*LL];
__device__ float g_nrr[BB*NH*LL];
__device__ float g_sw [BB*NH*LL];
__device__ float g_part[BB*16*DM];
__device__ float g_gate[BB*DM];

// pre-rounded (tf32 RNA) weights
#define OFF_TOK 0
#define SZ_TOK  196608
#define OFF_WQ  196608
#define SZ_QKVO 4194304
#define OFF_WK  4390912
#define OFF_WV  8585216
#define OFF_WO  12779520
#define OFF_C1  16973824
#define SZ_C    16777216
#define OFF_C2  33751040
#define WC_TOTAL 50528256
__device__ float g_wc[(size_t)WC_TOTAL];

// ---------------- helpers ----------------
__device__ __forceinline__ uint32_t smem_u32(const void* p) {
    uint32_t addr;
    asm("{ .reg .u64 tmp; cvta.to.shared.u64 tmp, %1; cvt.u32.u64 %0, tmp; }"
        : "=r"(addr) : "l"(p));
    return addr;
}

__device__ __forceinline__ float to_tf32(float x) {
    float r;
    asm("cvt.rna.tf32.f32 %0, %1;" : "=f"(r) : "f"(x));
    return r;
}

__device__ __forceinline__ unsigned cvt_u(float x) {
    unsigned r;
    asm("cvt.rna.tf32.f32 %0, %1;" : "=r"(r) : "f"(x));
    return r;
}

__device__ __forceinline__ void mma_tf32(float* d, const unsigned* a, const unsigned* b) {
    asm volatile(
        "mma.sync.aligned.m16n8k8.row.col.f32.tf32.tf32.f32 "
        "{%0,%1,%2,%3}, {%4,%5,%6,%7}, {%8,%9}, {%0,%1,%2,%3};"
        : "+f"(d[0]), "+f"(d[1]), "+f"(d[2]), "+f"(d[3])
        : "r"(a[0]), "r"(a[1]), "r"(a[2]), "r"(a[3]), "r"(b[0]), "r"(b[1]));
}

#define CP16(dst_u32, src_ptr) \
    asm volatile("cp.async.cg.shared.global [%0], [%1], 16;" \
                 :: "r"(dst_u32), "l"(src_ptr) : "memory")
#define CP_COMMIT() asm volatile("cp.async.commit_group;" ::: "memory")
#define CP_WAIT(n)  asm volatile("cp.async.wait_group %0;" :: "n"(n) : "memory")

// ---------------- weight pre-round: dst[i] = tf32_rna(src[i]) ----------------
__global__ void cvt_rna_kernel(const float* __restrict__ src, float* __restrict__ dst, int n)
{
    int i = (blockIdx.x * blockDim.x + threadIdx.x) * 4;
    if (i < n) {
        float4 v = *(const float4*)(src + i);
        v.x = to_tf32(v.x); v.y = to_tf32(v.y); v.z = to_tf32(v.z); v.w = to_tf32(v.w);
        *(float4*)(dst + i) = v;
    }
}

// ---------------- tf32 mma.sync GEMM: C[m,n] = sum_k A[m,k]*W[n,k] (+bias)(+res)(act)
// persistent CTAs, 128 threads, tile 128x128x32, warp tile 64x64,
// cp.async double-buffered. W must be pre-rounded to tf32; A rounded at fragment load.
#define SSTR 36
#define GT_SMEM (4*128*SSTR*4)   // 73728 bytes

__global__ __launch_bounds__(128, 2) void gemm_tc(
    const float* __restrict__ A, const float* __restrict__ W,
    const float* __restrict__ bias, const float* __restrict__ res,
    float* __restrict__ C, int Mm, int Nn, int Kk, int act)
{
    extern __shared__ float smem[];
    float* Asm[2] = { smem,               smem + 128*SSTR };
    float* Bsm[2] = { smem + 2*128*SSTR,  smem + 3*128*SSTR };
    uint32_t uA[2], uB[2];
    uA[0] = smem_u32(Asm[0]); uA[1] = smem_u32(Asm[1]);
    uB[0] = smem_u32(Bsm[0]); uB[1] = smem_u32(Bsm[1]);

    const int tid = threadIdx.x;
    const int warp = tid >> 5, lane = tid & 31;
    const int gid = lane >> 2, tig = lane & 3;
    const int wm = (warp & 1) * 64, wn = (warp >> 1) * 64;

    const int ntn = Nn / 128;
    const int ntiles = (Mm / 128) * ntn;
    const int T = Kk / 32;

    for (int tile = blockIdx.x; tile < ntiles; tile += gridDim.x) {
        const int bm = (tile / ntn) * 128;
        const int bn = (tile % ntn) * 128;

        float acc[4][8][4];
#pragma unroll
        for (int mi = 0; mi < 4; mi++)
#pragma unroll
            for (int ni = 0; ni < 8; ni++)
#pragma unroll
                for (int r = 0; r < 4; r++) acc[mi][ni][r] = 0.f;

        // prologue: k-tile 0 -> buf 0
#pragma unroll
        for (int j = 0; j < 8; j++) {
            int idx = tid + j * 128;
            int row = idx >> 3, qq = idx & 7;
            CP16(uA[0] + (uint32_t)(row * SSTR + qq * 4) * 4,
                 A + (size_t)(bm + row) * Kk + qq * 4);
            CP16(uB[0] + (uint32_t)(row * SSTR + qq * 4) * 4,
                 W + (size_t)(bn + row) * Kk + qq * 4);
        }
        CP_COMMIT();

        for (int t = 0; t < T; t++) {
            const int buf = t & 1;
            if (t + 1 < T) {
                const int k0 = (t + 1) * 32;
                const int nb = (t + 1) & 1;
#pragma unroll
                for (int j = 0; j < 8; j++) {
                    int idx = tid + j * 128;
                    int row = idx >> 3, qq = idx & 7;
                    CP16(uA[nb] + (uint32_t)(row * SSTR + qq * 4) * 4,
                         A + (size_t)(bm + row) * Kk + k0 + qq * 4);
                    CP16(uB[nb] + (uint32_t)(row * SSTR + qq * 4) * 4,
                         W + (size_t)(bn + row) * Kk + k0 + qq * 4);
                }
                CP_COMMIT();
                CP_WAIT(1);
            } else {
                CP_WAIT(0);
            }
            __syncthreads();

            const float* as = Asm[buf];
            const float* bs = Bsm[buf];
#pragma unroll
            for (int k8 = 0; k8 < 32; k8 += 8) {
                unsigned af[4][4], bf[8][2];
#pragma unroll
                for (int mi = 0; mi < 4; mi++) {
                    int r0 = wm + mi * 16 + gid;
                    af[mi][0] = cvt_u(as[r0 * SSTR + k8 + tig]);
                    af[mi][1] = cvt_u(as[(r0 + 8) * SSTR + k8 + tig]);
                    af[mi][2] = cvt_u(as[r0 * SSTR + k8 + tig + 4]);
                    af[mi][3] = cvt_u(as[(r0 + 8) * SSTR + k8 + tig + 4]);
                }
#pragma unroll
                for (int ni = 0; ni < 8; ni++) {
                    int c0 = wn + ni * 8 + gid;
                    bf[ni][0] = __float_as_uint(bs[c0 * SSTR + k8 + tig]);
                    bf[ni][1] = __float_as_uint(bs[c0 * SSTR + k8 + tig + 4]);
                }
#pragma unroll
                for (int mi = 0; mi < 4; mi++)
#pragma unroll
                    for (int ni = 0; ni < 8; ni++)
                        mma_tf32(acc[mi][ni], af[mi], bf[ni]);
            }
            __syncthreads();
        }

        // epilogue
#pragma unroll
        for (int mi = 0; mi < 4; mi++) {
            int row = bm + wm + mi * 16 + gid;
#pragma unroll
            for (int ni = 0; ni < 8; ni++) {
                int col = bn + wn + ni * 8 + 2 * tig;
                float b0 = 0.f, b1 = 0.f;
                if (bias) { b0 = bias[col]; b1 = bias[col + 1]; }
#pragma unroll
                for (int half = 0; half < 2; half++) {
                    int r = row + half * 8;
                    float v0 = acc[mi][ni][half * 2 + 0] + b0;
                    float v1 = acc[mi][ni][half * 2 + 1] + b1;
                    if (res) {
                        v0 += res[(size_t)r * Nn + col];
                        v1 += res[(size_t)r * Nn + col + 1];
                    }
                    if (act == ACT_RELU) { v0 = fmaxf(v0, 0.f); v1 = fmaxf(v1, 0.f); }
                    else if (act == ACT_SIG) {
                        v0 = 1.f / (1.f + expf(-v0));
                        v1 = 1.f / (1.f + expf(-v1));
                    }
                    *(float2*)(C + (size_t)r * Nn + col) = make_float2(v0, v1);
                }
            }
        }
    }
}

// ---------------- token embed gather ----------------
__global__ void gather192(const float* __restrict__ x, float* __restrict__ a)
{
    int m = blockIdx.x;
    int b = m / LL, l = m % LL;
    int t = threadIdx.x;          // 0..191
    int c = t / 3, kk = t % 3;
    int ll = l + kk - 1;
    ll = (ll + LL) % LL;
    a[(size_t)m * 192 + t] = x[((size_t)b * LL + ll) * CIN + c];
}

// ---------------- layer norm (1024), shuffle reductions + float4 I/O ----------------
__global__ __launch_bounds__(256) void ln_kernel(
    const float* __restrict__ x, const float* __restrict__ w,
    const float* __restrict__ b, float* __restrict__ out)
{
    __shared__ float s1[8], s2[8];
    const int m = blockIdx.x, tid = threadIdx.x;
    const int wid = tid >> 5, lane = tid & 31;
    const float* row = x + (size_t)m * DM;

    float4 v = *(const float4*)(row + tid * 4);
    float s = v.x + v.y + v.z + v.w;
#pragma unroll
    for (int o = 16; o >= 1; o >>= 1) s += __shfl_xor_sync(0xFFFFFFFFu, s, o);
    if (lane == 0) s1[wid] = s;
    __syncthreads();
    float tot = s1[0] + s1[1] + s1[2] + s1[3] + s1[4] + s1[5] + s1[6] + s1[7];
    const float mean = tot * (1.f / 1024.f);

    float dx = v.x - mean, dy = v.y - mean, dz = v.z - mean, dw = v.w - mean;
    float q = dx * dx + dy * dy + dz * dz + dw * dw;
#pragma unroll
    for (int o = 16; o >= 1; o >>= 1) q += __shfl_xor_sync(0xFFFFFFFFu, q, o);
    if (lane == 0) s2[wid] = q;
    __syncthreads();
    float qt = s2[0] + s2[1] + s2[2] + s2[3] + s2[4] + s2[5] + s2[6] + s2[7];
    const float inv = rsqrtf(qt * (1.f / 1024.f) + 1e-5f);

    float4 wv = *(const float4*)(w + tid * 4);
    float4 bv = *(const float4*)(b + tid * 4);
    float4 o4;
    o4.x = dx * inv * wv.x + bv.x;
    o4.y = dy * inv * wv.y + bv.y;
    o4.z = dz * inv * wv.z + bv.z;
    o4.w = dw * inv * wv.w + bv.w;
    *(float4*)(out + (size_t)m * DM + tid * 4) = o4;
}

// ---------------- flow attention: one block per (b,h) ----------------
__global__ __launch_bounds__(512) void flow_attn(
    const float* __restrict__ q, const float* __restrict__ k,
    const float* __restrict__ v, float* __restrict__ out,
    float* __restrict__ nr, float* __restrict__ nc,
    float* __restrict__ nrr, float* __restrict__ sw)
{
    const int bh = blockIdx.x;
    const int b = bh / NH, h = bh % NH;
    const size_t base = ((size_t)b * LL) * DM + (size_t)h * DH;
    const int tid = threadIdx.x;
    const float eps = 1e-6f;

    __shared__ float ksum[64], qsum[64], skn[64], sqn[64];
    __shared__ float red[512];
    __shared__ float kv[64][64];
    __shared__ float kt[32][64], vt[32][64], wt[32];

    const int d8 = tid & 63, ch = tid >> 6;

    // ---- step 1: ksum, qsum ----
    {
        float aq = 0.f, ak = 0.f;
        for (int l = ch; l < LL; l += 8) {
            size_t off = base + (size_t)l * DM + d8;
            aq += q[off]; ak += k[off];
        }
        red[tid] = aq; __syncthreads();
        for (int s = 4; s >= 1; s >>= 1) { if (ch < s) red[tid] += red[tid + (s<<6)]; __syncthreads(); }
        if (tid < 64) qsum[tid] = red[tid];
        __syncthreads();
        red[tid] = ak; __syncthreads();
        for (int s = 4; s >= 1; s >>= 1) { if (ch < s) red[tid] += red[tid + (s<<6)]; __syncthreads(); }
        if (tid < 64) ksum[tid] = red[tid];
        __syncthreads();
    }

    // ---- step 2: nr[l], nc[s] ----
    for (int l = tid; l < LL; l += 512) {
        const float4* q4 = (const float4*)(q + base + (size_t)l * DM);
        const float4* k4 = (const float4*)(k + base + (size_t)l * DM);
        float dq = 0.f, dk = 0.f;
#pragma unroll
        for (int d = 0; d < 16; d++) {
            float4 qv = q4[d], kvv = k4[d];
            float4 ks4 = *(const float4*)&ksum[d * 4];
            float4 qs4 = *(const float4*)&qsum[d * 4];
            dq += (qv.x + eps) * (ks4.x + eps) + (qv.y + eps) * (ks4.y + eps)
                + (qv.z + eps) * (ks4.z + eps) + (qv.w + eps) * (ks4.w + eps);
            dk += (kvv.x + eps) * (qs4.x + eps) + (kvv.y + eps) * (qs4.y + eps)
                + (kvv.z + eps) * (qs4.z + eps) + (kvv.w + eps) * (qs4.w + eps);
        }
        nr[bh*LL + l] = 1.f / dq;
        nc[bh*LL + l] = 1.f / dk;
    }
    __syncthreads();

    // ---- step 3: skn = sum_s k*nc ; sqn = sum_l q*nr ----
    {
        float a1 = 0.f, a2 = 0.f;
        for (int l = ch; l < LL; l += 8) {
            size_t off = base + (size_t)l * DM + d8;
            a1 += k[off] * nc[bh*LL + l];
            a2 += q[off] * nr[bh*LL + l];
        }
        red[tid] = a1; __syncthreads();
        for (int s = 4; s >= 1; s >>= 1) { if (ch < s) red[tid] += red[tid + (s<<6)]; __syncthreads(); }
        if (tid < 64) skn[tid] = red[tid];
        __syncthreads();
        red[tid] = a2; __syncthreads();
        for (int s = 4; s >= 1; s >>= 1) { if (ch < s) red[tid] += red[tid + (s<<6)]; __syncthreads(); }
        if (tid < 64) sqn[tid] = red[tid];
        __syncthreads();
    }

    // ---- step 4: ncr (softmax*L), nrr ----
    float lmax = -1e30f;
    for (int l = tid; l < LL; l += 512) {
        const float4* k4 = (const float4*)(k + base + (size_t)l * DM);
        const float4* q4 = (const float4*)(q + base + (size_t)l * DM);
        float dc = 0.f, dr = 0.f;
#pragma unroll
        for (int d = 0; d < 16; d++) {
            float4 kvv = k4[d], qv = q4[d];
            float4 sq4 = *(const float4*)&sqn[d * 4];
            float4 sk4 = *(const float4*)&skn[d * 4];
            dc += (kvv.x + eps) * (sq4.x + eps) + (kvv.y + eps) * (sq4.y + eps)
                + (kvv.z + eps) * (sq4.z + eps) + (kvv.w + eps) * (sq4.w + eps);
            dr += (qv.x + eps) * (sk4.x + eps) + (qv.y + eps) * (sk4.y + eps)
                + (qv.z + eps) * (sk4.z + eps) + (qv.w + eps) * (sk4.w + eps);
        }
        sw[bh*LL + l] = dc;
        nrr[bh*LL + l] = 1.f / (1.f + expf(-dr));
        lmax = fmaxf(lmax, dc);
    }
    red[tid] = lmax; __syncthreads();
    for (int s = 256; s >= 1; s >>= 1) { if (tid < s) red[tid] = fmaxf(red[tid], red[tid + s]); __syncthreads(); }
    float mx = red[0];
    __syncthreads();
    float lsum = 0.f;
    for (int l = tid; l < LL; l += 512) {
        float e = expf(sw[bh*LL + l] - mx);
        sw[bh*LL + l] = e;
        lsum += e;
    }
    red[tid] = lsum; __syncthreads();
    for (int s = 256; s >= 1; s >>= 1) { if (tid < s) red[tid] += red[tid + s]; __syncthreads(); }
    const float wfac = (float)LL / red[0];
    __syncthreads();

    // ---- step 5: kv[d][e] = sum_s k[s,d] * (v[s,e] * w[s]) ----
    {
        float acc[8];
#pragma unroll
        for (int j = 0; j < 8; j++) acc[j] = 0.f;
        const int dd = tid >> 3, e0 = (tid & 7) << 3;
        const int ssg = tid >> 4, ccg = (tid & 15) << 2;
        for (int s0 = 0; s0 < LL; s0 += 32) {
            *(float4*)&kt[ssg][ccg] = *(const float4*)(k + base + (size_t)(s0 + ssg) * DM + ccg);
            *(float4*)&vt[ssg][ccg] = *(const float4*)(v + base + (size_t)(s0 + ssg) * DM + ccg);
            if (tid < 32) wt[tid] = sw[bh*LL + s0 + tid] * wfac;
            __syncthreads();
#pragma unroll 8
            for (int ss = 0; ss < 32; ss++) {
                float kw = kt[ss][dd] * wt[ss];
                float4 va = *(const float4*)&vt[ss][e0];
                float4 vb = *(const float4*)&vt[ss][e0 + 4];
                acc[0] = fmaf(kw, va.x, acc[0]); acc[1] = fmaf(kw, va.y, acc[1]);
                acc[2] = fmaf(kw, va.z, acc[2]); acc[3] = fmaf(kw, va.w, acc[3]);
                acc[4] = fmaf(kw, vb.x, acc[4]); acc[5] = fmaf(kw, vb.y, acc[5]);
                acc[6] = fmaf(kw, vb.z, acc[6]); acc[7] = fmaf(kw, vb.w, acc[7]);
            }
            __syncthreads();
        }
#pragma unroll
        for (int j = 0; j < 8; j++) kv[dd][e0 + j] = acc[j];
        __syncthreads();
    }

    // ---- step 6: out[l,e] = (q[l,:] . kv[:,e]) * nr[l] * nrr[l] ----
    // chunks of 32 l staged in kt; thread computes 2l x {eq, eq+32}
    {
        const int ssg = tid >> 4, ccg = (tid & 15) << 2;
        const int lq = tid >> 5, eq = tid & 31;
        for (int s0 = 0; s0 < LL; s0 += 32) {
            *(float4*)&kt[ssg][ccg] = *(const float4*)(q + base + (size_t)(s0 + ssg) * DM + ccg);
            __syncthreads();
            const int l0 = lq * 2;
            float a00 = 0.f, a01 = 0.f, a10 = 0.f, a11 = 0.f;
#pragma unroll
            for (int d = 0; d < 64; d += 4) {
                float4 qa = *(const float4*)&kt[l0][d];
                float4 qb = *(const float4*)&kt[l0 + 1][d];
                float k0a = kv[d][eq],     k0b = kv[d][eq + 32];
                float k1a = kv[d + 1][eq], k1b = kv[d + 1][eq + 32];
                float k2a = kv[d + 2][eq], k2b = kv[d + 2][eq + 32];
                float k3a = kv[d + 3][eq], k3b = kv[d + 3][eq + 32];
                a00 = fmaf(qa.x, k0a, a00); a00 = fmaf(qa.y, k1a, a00);
                a00 = fmaf(qa.z, k2a, a00); a00 = fmaf(qa.w, k3a, a00);
                a01 = fmaf(qa.x, k0b, a01); a01 = fmaf(qa.y, k1b, a01);
                a01 = fmaf(qa.z, k2b, a01); a01 = fmaf(qa.w, k3b, a01);
                a10 = fmaf(qb.x, k0a, a10); a10 = fmaf(qb.y, k1a, a10);
                a10 = fmaf(qb.z, k2a, a10); a10 = fmaf(qb.w, k3a, a10);
                a11 = fmaf(qb.x, k0b, a11); a11 = fmaf(qb.y, k1b, a11);
                a11 = fmaf(qb.z, k2b, a11); a11 = fmaf(qb.w, k3b, a11);
            }
            const int gl0 = s0 + l0;
            float f0 = nr[bh*LL + gl0] * nrr[bh*LL + gl0];
            float f1 = nr[bh*LL + gl0 + 1] * nrr[bh*LL + gl0 + 1];
            out[base + (size_t)gl0 * DM + eq]            = a00 * f0;
            out[base + (size_t)gl0 * DM + eq + 32]       = a01 * f0;
            out[base + (size_t)(gl0 + 1) * DM + eq]      = a10 * f1;
            out[base + (size_t)(gl0 + 1) * DM + eq + 32] = a11 * f1;
            __syncthreads();
        }
    }
}

// ---------------- channel attention ----------------
__global__ __launch_bounds__(1024) void ca_partial(const float* __restrict__ x, float* __restrict__ part)
{
    int b = blockIdx.x, chk = blockIdx.y, c = threadIdx.x;
    float s = 0.f;
    int l0 = chk * 128;
    for (int l = l0; l < l0 + 128; l++) s += x[((size_t)b * LL + l) * DM + c];
    part[((size_t)b * 16 + chk) * DM + c] = s;
}

__global__ __launch_bounds__(1024) void ca_gate(const float* __restrict__ part,
                                                const float* __restrict__ caw,
                                                float* __restrict__ gate)
{
    __shared__ float m[DM + 4];
    int b = blockIdx.x, c = threadIdx.x;
    float s = 0.f;
    for (int p = 0; p < 16; p++) s += part[((size_t)b * 16 + p) * DM + c];
    m[c + 2] = s * (1.f / (float)LL);
    if (c < 2) m[c] = 0.f;
    if (c >= DM - 2) m[c + 4] = 0.f;
    __syncthreads();
    float g = 0.f;
#pragma unroll
    for (int kk = 0; kk < 5; kk++) g += caw[kk] * m[c + kk];
    gate[(size_t)b * DM + c] = 1.f / (1.f + expf(-g));
}

__global__ __launch_bounds__(1024) void ca_mul(float* __restrict__ x, const float* __restrict__ gate)
{
    int mrow = blockIdx.x;
    int b = mrow / LL;
    int c = threadIdx.x;
    x[(size_t)mrow * DM + c] *= gate[(size_t)b * DM + c];
}

// ---------------- final projection ----------------
__global__ __launch_bounds__(64) void proj_kernel(const float* __restrict__ hln,
                                                  const float* __restrict__ pw,
                                                  const float* __restrict__ pb,
                                                  float* __restrict__ out)
{
    int m = blockIdx.x, n = threadIdx.x;
    const float* hr = hln + (size_t)m * DM;
    const float* wr = pw + (size_t)n * DM;
    float a = 0.f;
    const float4* h4 = (const float4*)hr;
    const float4* w4 = (const float4*)wr;
#pragma unroll 4
    for (int kk = 0; kk < DM/4; kk++) {
        float4 hv = h4[kk], wv = w4[kk];
        a += hv.x*wv.x + hv.y*wv.y + hv.z*wv.z + hv.w*wv.w;
    }
    out[(size_t)m * COUTN + n] = a + pb[n];
}

// ---------------- host ----------------
static inline void cvt_launch(const float* src, float* dst, int n)
{
    int nt = n / 4;
    cvt_rna_kernel<<<(nt + 255) / 256, 256>>>(src, dst, n);
}

extern "C" void kernel_launch(void* const* d_in, const int* in_sizes, int n_in,
                              void* d_out, int out_size)
{
    const float* x    = (const float*)d_in[0];
    const float* tokw = (const float*)d_in[1];
    const float* Wq   = (const float*)d_in[2];
    const float* bq   = (const float*)d_in[3];
    const float* Wk   = (const float*)d_in[4];
    const float* bk   = (const float*)d_in[5];
    const float* Wv   = (const float*)d_in[6];
    const float* bv   = (const float*)d_in[7];
    const float* Wo   = (const float*)d_in[8];
    const float* bo   = (const float*)d_in[9];
    const float* c1w  = (const float*)d_in[10];
    const float* c1b  = (const float*)d_in[11];
    const float* c2w  = (const float*)d_in[12];
    const float* c2b  = (const float*)d_in[13];
    const float* ln1w = (const float*)d_in[14];
    const float* ln1b = (const float*)d_in[15];
    const float* ln2w = (const float*)d_in[16];
    const float* ln2b = (const float*)d_in[17];
    const float* caw  = (const float*)d_in[18];
    const float* lnfw = (const float*)d_in[19];
    const float* lnfb = (const float*)d_in[20];
    const float* pw   = (const float*)d_in[21];
    const float* pb   = (const float*)d_in[22];

    float *p_in192, *p_h, *p_h2, *p_q, *p_k, *p_v, *p_a, *p_t;
    float *p_nr, *p_nc, *p_nrr, *p_sw, *p_part, *p_gate, *p_wc;
    cudaGetSymbolAddress((void**)&p_in192, g_in192);
    cudaGetSymbolAddress((void**)&p_h,  g_h);
    cudaGetSymbolAddress((void**)&p_h2, g_h2);
    cudaGetSymbolAddress((void**)&p_q,  g_q);
    cudaGetSymbolAddress((void**)&p_k,  g_k);
    cudaGetSymbolAddress((void**)&p_v,  g_v);
    cudaGetSymbolAddress((void**)&p_a,  g_a);
    cudaGetSymbolAddress((void**)&p_t,  g_t);
    cudaGetSymbolAddress((void**)&p_nr,  g_nr);
    cudaGetSymbolAddress((void**)&p_nc,  g_nc);
    cudaGetSymbolAddress((void**)&p_nrr, g_nrr);
    cudaGetSymbolAddress((void**)&p_sw,  g_sw);
    cudaGetSymbolAddress((void**)&p_part, g_part);
    cudaGetSymbolAddress((void**)&p_gate, g_gate);
    cudaGetSymbolAddress((void**)&p_wc,  g_wc);

    cudaFuncSetAttribute(gemm_tc, cudaFuncAttributeMaxDynamicSharedMemorySize, GT_SMEM);

    // pre-round all GEMM weights to tf32 (RNA)
    cvt_launch(tokw, p_wc + OFF_TOK, SZ_TOK);
    cvt_launch(Wq,   p_wc + OFF_WQ,  SZ_QKVO);
    cvt_launch(Wk,   p_wc + OFF_WK,  SZ_QKVO);
    cvt_launch(Wv,   p_wc + OFF_WV,  SZ_QKVO);
    cvt_launch(Wo,   p_wc + OFF_WO,  SZ_QKVO);
    cvt_launch(c1w,  p_wc + OFF_C1,  SZ_C);
    cvt_launch(c2w,  p_wc + OFF_C2,  SZ_C);

    const int GRID = 296;   // 2 persistent CTAs per SM (148 SMs)

    // token embedding (circular conv k=3) as gather + GEMM (K=192)
    gather192<<<MM, 192>>>(x, p_in192);
    gemm_tc<<<GRID, 128, GT_SMEM>>>(p_in192, p_wc + OFF_TOK, nullptr, nullptr,
                                    p_h, MM, DM, 192, ACT_NONE);

    for (int rep = 0; rep < 5; rep++) {
        int i = (rep < 4) ? rep : 3;
        const float* wq = p_wc + OFF_WQ + (size_t)i * 1048576;
        const float* wk = p_wc + OFF_WK + (size_t)i * 1048576;
        const float* wv = p_wc + OFF_WV + (size_t)i * 1048576;
        const float* wo = p_wc + OFF_WO + (size_t)i * 1048576;
        const float* w1 = p_wc + OFF_C1 + (size_t)i * (FF * DM);
        const float* w2 = p_wc + OFF_C2 + (size_t)i * (FF * DM);

        gemm_tc<<<GRID, 128, GT_SMEM>>>(p_h, wq, bq + i*DM, nullptr, p_q, MM, DM, DM, ACT_SIG);
        gemm_tc<<<GRID, 128, GT_SMEM>>>(p_h, wk, bk + i*DM, nullptr, p_k, MM, DM, DM, ACT_SIG);
        gemm_tc<<<GRID, 128, GT_SMEM>>>(p_h, wv, bv + i*DM, nullptr, p_v, MM, DM, DM, ACT_NONE);

        flow_attn<<<BB*NH, 512>>>(p_q, p_k, p_v, p_a, p_nr, p_nc, p_nrr, p_sw);

        gemm_tc<<<GRID, 128, GT_SMEM>>>(p_a, wo, bo + i*DM, p_h, p_q, MM, DM, DM, ACT_NONE);
        ln_kernel<<<MM, 256>>>(p_q, ln1w + i*DM, ln1b + i*DM, p_h2);

        gemm_tc<<<GRID, 128, GT_SMEM>>>(p_h2, w1, c1b + i*FF, nullptr, p_t, MM, FF, DM, ACT_RELU);
        gemm_tc<<<GRID, 128, GT_SMEM>>>(p_t, w2, c2b + i*DM, p_h2, p_q, MM, DM, FF, ACT_NONE);
        ln_kernel<<<MM, 256>>>(p_q, ln2w + i*DM, ln2b + i*DM, p_h);

        if (rep < 4) {
            ca_partial<<<dim3(BB, 16), 1024>>>(p_h, p_part);
            ca_gate<<<BB, 1024>>>(p_part, caw + i*5, p_gate);
            ca_mul<<<MM, 1024>>>(p_h, p_gate);
        }
    }

    ln_kernel<<<MM, 256>>>(p_h, lnfw, lnfb, p_h2);
    proj_kernel<<<MM, 64>>>(p_h2, pw, pb, (float*)d_out);
}

// round 6
// speedup vs baseline: 2.6125x; 1.0133x over previous
#include <cuda_runtime.h>
#include <math.h>
#include <stdint.h>

#define BB 4
#define LL 2048
#define CIN 64
#define COUTN 64
#define DM 1024
#define NH 16
#define DH 64
#define FF 4096
#define MM (BB*LL)

#define ACT_NONE 0
#define ACT_RELU 1
#define ACT_SIG  2

// ---------------- scratch (device globals; no cudaMalloc allowed) ----------------
__device__ float g_in192[(size_t)MM*192];
__device__ float g_h [(size_t)MM*DM];
__device__ float g_h2[(size_t)MM*DM];
__device__ float g_q [(size_t)MM*DM];
__device__ float g_k [(size_t)MM*DM];
__device__ float g_v [(size_t)MM*DM];
__device__ float g_a [(size_t)MM*DM];
__device__ float g_t [(size_t)MM*FF];
__device__ float g_nr [BB*NH*LL];
__device__ float g_nc [BB*NH*LL];
__device__ float g_nrr[BB*NH*LL];
__device__ float g_sw [BB*NH*LL];
__device__ float g_part[BB*16*DM];
__device__ float g_gate[BB*DM];

// pre-rounded (tf32 RNA) weights
#define OFF_TOK 0
#define SZ_TOK  196608
#define OFF_WQ  196608
#define SZ_QKVO 4194304
#define OFF_WK  4390912
#define OFF_WV  8585216
#define OFF_WO  12779520
#define OFF_C1  16973824
#define SZ_C    16777216
#define OFF_C2  33751040
#define WC_TOTAL 50528256
__device__ float g_wc[(size_t)WC_TOTAL];

// ---------------- helpers ----------------
__device__ __forceinline__ uint32_t smem_u32(const void* p) {
    uint32_t addr;
    asm("{ .reg .u64 tmp; cvta.to.shared.u64 tmp, %1; cvt.u32.u64 %0, tmp; }"
        : "=r"(addr) : "l"(p));
    return addr;
}

__device__ __forceinline__ float to_tf32(float x) {
    float r;
    asm("cvt.rna.tf32.f32 %0, %1;" : "=f"(r) : "f"(x));
    return r;
}

__device__ __forceinline__ void mma_tf32(float* d, const unsigned* a, const unsigned* b) {
    asm volatile(
        "mma.sync.aligned.m16n8k8.row.col.f32.tf32.tf32.f32 "
        "{%0,%1,%2,%3}, {%4,%5,%6,%7}, {%8,%9}, {%0,%1,%2,%3};"
        : "+f"(d[0]), "+f"(d[1]), "+f"(d[2]), "+f"(d[3])
        : "r"(a[0]), "r"(a[1]), "r"(a[2]), "r"(a[3]), "r"(b[0]), "r"(b[1]));
}

#define CP16(dst_u32, src_ptr) \
    asm volatile("cp.async.cg.shared.global [%0], [%1], 16;" \
                 :: "r"(dst_u32), "l"(src_ptr) : "memory")
#define CP_COMMIT() asm volatile("cp.async.commit_group;" ::: "memory")
#define CP_WAIT(n)  asm volatile("cp.async.wait_group %0;" :: "n"(n) : "memory")

// ---------------- weight pre-round: dst[i] = tf32_rna(src[i]) ----------------
__global__ void cvt_rna_kernel(const float* __restrict__ src, float* __restrict__ dst, int n)
{
    int i = (blockIdx.x * blockDim.x + threadIdx.x) * 4;
    if (i < n) {
        float4 v = *(const float4*)(src + i);
        v.x = to_tf32(v.x); v.y = to_tf32(v.y); v.z = to_tf32(v.z); v.w = to_tf32(v.w);
        *(float4*)(dst + i) = v;
    }
}

// ---------------- tf32 mma.sync GEMM: C[m,n] = sum_k A[m,k]*W[n,k] (+bias)(+res)(act)
// persistent CTAs, 256 threads (8 warps, 2x4 grid, warp tile 64x32),
// tile 128x128x32, double-buffered.
// A: LDG -> RNA cvt -> STS (registers). W: pre-rounded, cp.async direct to smem.
#define SSTR 36
#define GT_SMEM (4*128*SSTR*4)   // 73728 bytes

__global__ __launch_bounds__(256, 2) void gemm_tc(
    const float* __restrict__ A, const float* __restrict__ W,
    const float* __restrict__ bias, const float* __restrict__ res,
    float* __restrict__ C, int Mm, int Nn, int Kk, int act)
{
    extern __shared__ float smem[];
    float* Asm[2] = { smem,               smem + 128*SSTR };
    float* Bsm[2] = { smem + 2*128*SSTR,  smem + 3*128*SSTR };
    uint32_t uB[2];
    uB[0] = smem_u32(Bsm[0]); uB[1] = smem_u32(Bsm[1]);

    const int tid = threadIdx.x;
    const int warp = tid >> 5, lane = tid & 31;
    const int gid = lane >> 2, tig = lane & 3;
    const int wm = (warp & 1) * 64;      // 2 warps across m
    const int wn = (warp >> 1) * 32;     // 4 warps across n

    const int ntn = Nn / 128;
    const int ntiles = (Mm / 128) * ntn;
    const int T = Kk / 32;

    // per-thread A staging slots
    int rowi[4], qi[4];
#pragma unroll
    for (int j = 0; j < 4; j++) {
        int idx = tid + j * 256;
        rowi[j] = idx >> 3;
        qi[j] = idx & 7;
    }

    for (int tile = blockIdx.x; tile < ntiles; tile += gridDim.x) {
        const int bm = (tile / ntn) * 128;
        const int bn = (tile % ntn) * 128;

        float acc[4][4][4];
#pragma unroll
        for (int mi = 0; mi < 4; mi++)
#pragma unroll
            for (int ni = 0; ni < 4; ni++)
#pragma unroll
                for (int r = 0; r < 4; r++) acc[mi][ni][r] = 0.f;

        // prologue: A regs for t=0, cp.async B tile 0
        float4 ra[4];
#pragma unroll
        for (int j = 0; j < 4; j++) {
            ra[j] = *(const float4*)(A + (size_t)(bm + rowi[j]) * Kk + qi[j] * 4);
            CP16(uB[0] + (uint32_t)(rowi[j] * SSTR + qi[j] * 4) * 4,
                 W + (size_t)(bn + rowi[j]) * Kk + qi[j] * 4);
        }
        CP_COMMIT();

        for (int t = 0; t < T; t++) {
            const int buf = t & 1;

            // store staged A (RNA-rounded) into smem buffer
#pragma unroll
            for (int j = 0; j < 4; j++) {
                float4 va = ra[j];
                va.x = to_tf32(va.x); va.y = to_tf32(va.y);
                va.z = to_tf32(va.z); va.w = to_tf32(va.w);
                *(float4*)(Asm[buf] + rowi[j] * SSTR + qi[j] * 4) = va;
            }

            // prefetch next tile
            if (t + 1 < T) {
                const int k0 = (t + 1) * 32;
                const int nb = (t + 1) & 1;
#pragma unroll
                for (int j = 0; j < 4; j++) {
                    ra[j] = *(const float4*)(A + (size_t)(bm + rowi[j]) * Kk + k0 + qi[j] * 4);
                    CP16(uB[nb] + (uint32_t)(rowi[j] * SSTR + qi[j] * 4) * 4,
                         W + (size_t)(bn + rowi[j]) * Kk + k0 + qi[j] * 4);
                }
                CP_COMMIT();
                CP_WAIT(1);
            } else {
                CP_WAIT(0);
            }
            __syncthreads();

            const unsigned* as = (const unsigned*)Asm[buf];
            const unsigned* bs = (const unsigned*)Bsm[buf];
#pragma unroll
            for (int k8 = 0; k8 < 32; k8 += 8) {
                unsigned af[4][4], bf[4][2];
#pragma unroll
                for (int mi = 0; mi < 4; mi++) {
                    int r0 = wm + mi * 16 + gid;
                    af[mi][0] = as[r0 * SSTR + k8 + tig];
                    af[mi][1] = as[(r0 + 8) * SSTR + k8 + tig];
                    af[mi][2] = as[r0 * SSTR + k8 + tig + 4];
                    af[mi][3] = as[(r0 + 8) * SSTR + k8 + tig + 4];
                }
#pragma unroll
                for (int ni = 0; ni < 4; ni++) {
                    int c0 = wn + ni * 8 + gid;
                    bf[ni][0] = bs[c0 * SSTR + k8 + tig];
                    bf[ni][1] = bs[c0 * SSTR + k8 + tig + 4];
                }
#pragma unroll
                for (int mi = 0; mi < 4; mi++)
#pragma unroll
                    for (int ni = 0; ni < 4; ni++)
                        mma_tf32(acc[mi][ni], af[mi], bf[ni]);
            }
            __syncthreads();
        }

        // epilogue
#pragma unroll
        for (int mi = 0; mi < 4; mi++) {
            int row = bm + wm + mi * 16 + gid;
#pragma unroll
            for (int ni = 0; ni < 4; ni++) {
                int col = bn + wn + ni * 8 + 2 * tig;
                float b0 = 0.f, b1 = 0.f;
                if (bias) { b0 = bias[col]; b1 = bias[col + 1]; }
#pragma unroll
                for (int half = 0; half < 2; half++) {
                    int r = row + half * 8;
                    float v0 = acc[mi][ni][half * 2 + 0] + b0;
                    float v1 = acc[mi][ni][half * 2 + 1] + b1;
                    if (res) {
                        v0 += res[(size_t)r * Nn + col];
                        v1 += res[(size_t)r * Nn + col + 1];
                    }
                    if (act == ACT_RELU) { v0 = fmaxf(v0, 0.f); v1 = fmaxf(v1, 0.f); }
                    else if (act == ACT_SIG) {
                        v0 = 1.f / (1.f + expf(-v0));
                        v1 = 1.f / (1.f + expf(-v1));
                    }
                    *(float2*)(C + (size_t)r * Nn + col) = make_float2(v0, v1);
                }
            }
        }
    }
}

// ---------------- token embed gather ----------------
__global__ void gather192(const float* __restrict__ x, float* __restrict__ a)
{
    int m = blockIdx.x;
    int b = m / LL, l = m % LL;
    int t = threadIdx.x;          // 0..191
    int c = t / 3, kk = t % 3;
    int ll = l + kk - 1;
    ll = (ll + LL) % LL;
    a[(size_t)m * 192 + t] = x[((size_t)b * LL + ll) * CIN + c];
}

// ---------------- layer norm (1024), shuffle reductions + float4 I/O ----------------
__global__ __launch_bounds__(256) void ln_kernel(
    const float* __restrict__ x, const float* __restrict__ w,
    const float* __restrict__ b, float* __restrict__ out)
{
    __shared__ float s1[8], s2[8];
    const int m = blockIdx.x, tid = threadIdx.x;
    const int wid = tid >> 5, lane = tid & 31;
    const float* row = x + (size_t)m * DM;

    float4 v = *(const float4*)(row + tid * 4);
    float s = v.x + v.y + v.z + v.w;
#pragma unroll
    for (int o = 16; o >= 1; o >>= 1) s += __shfl_xor_sync(0xFFFFFFFFu, s, o);
    if (lane == 0) s1[wid] = s;
    __syncthreads();
    float tot = s1[0] + s1[1] + s1[2] + s1[3] + s1[4] + s1[5] + s1[6] + s1[7];
    const float mean = tot * (1.f / 1024.f);

    float dx = v.x - mean, dy = v.y - mean, dz = v.z - mean, dw = v.w - mean;
    float q = dx * dx + dy * dy + dz * dz + dw * dw;
#pragma unroll
    for (int o = 16; o >= 1; o >>= 1) q += __shfl_xor_sync(0xFFFFFFFFu, q, o);
    if (lane == 0) s2[wid] = q;
    __syncthreads();
    float qt = s2[0] + s2[1] + s2[2] + s2[3] + s2[4] + s2[5] + s2[6] + s2[7];
    const float inv = rsqrtf(qt * (1.f / 1024.f) + 1e-5f);

    float4 wv = *(const float4*)(w + tid * 4);
    float4 bv = *(const float4*)(b + tid * 4);
    float4 o4;
    o4.x = dx * inv * wv.x + bv.x;
    o4.y = dy * inv * wv.y + bv.y;
    o4.z = dz * inv * wv.z + bv.z;
    o4.w = dw * inv * wv.w + bv.w;
    *(float4*)(out + (size_t)m * DM + tid * 4) = o4;
}

// ---------------- flow attention: one block per (b,h) ----------------
__global__ __launch_bounds__(512) void flow_attn(
    const float* __restrict__ q, const float* __restrict__ k,
    const float* __restrict__ v, float* __restrict__ out,
    float* __restrict__ nr, float* __restrict__ nc,
    float* __restrict__ nrr, float* __restrict__ sw)
{
    const int bh = blockIdx.x;
    const int b = bh / NH, h = bh % NH;
    const size_t base = ((size_t)b * LL) * DM + (size_t)h * DH;
    const int tid = threadIdx.x;
    const float eps = 1e-6f;

    __shared__ float ksum[64], qsum[64], skn[64], sqn[64];
    __shared__ float red[512];
    __shared__ float kv[64][64];
    __shared__ float kt[32][64], vt[32][64], wt[32];

    const int d8 = tid & 63, ch = tid >> 6;

    // ---- step 1: ksum, qsum ----
    {
        float aq = 0.f, ak = 0.f;
        for (int l = ch; l < LL; l += 8) {
            size_t off = base + (size_t)l * DM + d8;
            aq += q[off]; ak += k[off];
        }
        red[tid] = aq; __syncthreads();
        for (int s = 4; s >= 1; s >>= 1) { if (ch < s) red[tid] += red[tid + (s<<6)]; __syncthreads(); }
        if (tid < 64) qsum[tid] = red[tid];
        __syncthreads();
        red[tid] = ak; __syncthreads();
        for (int s = 4; s >= 1; s >>= 1) { if (ch < s) red[tid] += red[tid + (s<<6)]; __syncthreads(); }
        if (tid < 64) ksum[tid] = red[tid];
        __syncthreads();
    }

    // ---- step 2: nr[l], nc[s] ----
    for (int l = tid; l < LL; l += 512) {
        const float4* q4 = (const float4*)(q + base + (size_t)l * DM);
        const float4* k4 = (const float4*)(k + base + (size_t)l * DM);
        float dq = 0.f, dk = 0.f;
#pragma unroll
        for (int d = 0; d < 16; d++) {
            float4 qv = q4[d], kvv = k4[d];
            float4 ks4 = *(const float4*)&ksum[d * 4];
            float4 qs4 = *(const float4*)&qsum[d * 4];
            dq += (qv.x + eps) * (ks4.x + eps) + (qv.y + eps) * (ks4.y + eps)
                + (qv.z + eps) * (ks4.z + eps) + (qv.w + eps) * (ks4.w + eps);
            dk += (kvv.x + eps) * (qs4.x + eps) + (kvv.y + eps) * (qs4.y + eps)
                + (kvv.z + eps) * (qs4.z + eps) + (kvv.w + eps) * (qs4.w + eps);
        }
        nr[bh*LL + l] = 1.f / dq;
        nc[bh*LL + l] = 1.f / dk;
    }
    __syncthreads();

    // ---- step 3: skn = sum_s k*nc ; sqn = sum_l q*nr ----
    {
        float a1 = 0.f, a2 = 0.f;
        for (int l = ch; l < LL; l += 8) {
            size_t off = base + (size_t)l * DM + d8;
            a1 += k[off] * nc[bh*LL + l];
            a2 += q[off] * nr[bh*LL + l];
        }
        red[tid] = a1; __syncthreads();
        for (int s = 4; s >= 1; s >>= 1) { if (ch < s) red[tid] += red[tid + (s<<6)]; __syncthreads(); }
        if (tid < 64) skn[tid] = red[tid];
        __syncthreads();
        red[tid] = a2; __syncthreads();
        for (int s = 4; s >= 1; s >>= 1) { if (ch < s) red[tid] += red[tid + (s<<6)]; __syncthreads(); }
        if (tid < 64) sqn[tid] = red[tid];
        __syncthreads();
    }

    // ---- step 4: ncr (softmax*L), nrr ----
    float lmax = -1e30f;
    for (int l = tid; l < LL; l += 512) {
        const float4* k4 = (const float4*)(k + base + (size_t)l * DM);
        const float4* q4 = (const float4*)(q + base + (size_t)l * DM);
        float dc = 0.f, dr = 0.f;
#pragma unroll
        for (int d = 0; d < 16; d++) {
            float4 kvv = k4[d], qv = q4[d];
            float4 sq4 = *(const float4*)&sqn[d * 4];
            float4 sk4 = *(const float4*)&skn[d * 4];
            dc += (kvv.x + eps) * (sq4.x + eps) + (kvv.y + eps) * (sq4.y + eps)
                + (kvv.z + eps) * (sq4.z + eps) + (kvv.w + eps) * (sq4.w + eps);
            dr += (qv.x + eps) * (sk4.x + eps) + (qv.y + eps) * (sk4.y + eps)
                + (qv.z + eps) * (sk4.z + eps) + (qv.w + eps) * (sk4.w + eps);
        }
        sw[bh*LL + l] = dc;
        nrr[bh*LL + l] = 1.f / (1.f + expf(-dr));
        lmax = fmaxf(lmax, dc);
    }
    red[tid] = lmax; __syncthreads();
    for (int s = 256; s >= 1; s >>= 1) { if (tid < s) red[tid] = fmaxf(red[tid], red[tid + s]); __syncthreads(); }
    float mx = red[0];
    __syncthreads();
    float lsum = 0.f;
    for (int l = tid; l < LL; l += 512) {
        float e = expf(sw[bh*LL + l] - mx);
        sw[bh*LL + l] = e;
        lsum += e;
    }
    red[tid] = lsum; __syncthreads();
    for (int s = 256; s >= 1; s >>= 1) { if (tid < s) red[tid] += red[tid + s]; __syncthreads(); }
    const float wfac = (float)LL / red[0];
    __syncthreads();

    // ---- step 5: kv[d][e] = sum_s k[s,d] * (v[s,e] * w[s]) ----
    {
        float acc[8];
#pragma unroll
        for (int j = 0; j < 8; j++) acc[j] = 0.f;
        const int dd = tid >> 3, e0 = (tid & 7) << 3;
        const int ssg = tid >> 4, ccg = (tid & 15) << 2;
        for (int s0 = 0; s0 < LL; s0 += 32) {
            *(float4*)&kt[ssg][ccg] = *(const float4*)(k + base + (size_t)(s0 + ssg) * DM + ccg);
            *(float4*)&vt[ssg][ccg] = *(const float4*)(v + base + (size_t)(s0 + ssg) * DM + ccg);
            if (tid < 32) wt[tid] = sw[bh*LL + s0 + tid] * wfac;
            __syncthreads();
#pragma unroll 8
            for (int ss = 0; ss < 32; ss++) {
                float kw = kt[ss][dd] * wt[ss];
                float4 va = *(const float4*)&vt[ss][e0];
                float4 vb = *(const float4*)&vt[ss][e0 + 4];
                acc[0] = fmaf(kw, va.x, acc[0]); acc[1] = fmaf(kw, va.y, acc[1]);
                acc[2] = fmaf(kw, va.z, acc[2]); acc[3] = fmaf(kw, va.w, acc[3]);
                acc[4] = fmaf(kw, vb.x, acc[4]); acc[5] = fmaf(kw, vb.y, acc[5]);
                acc[6] = fmaf(kw, vb.z, acc[6]); acc[7] = fmaf(kw, vb.w, acc[7]);
            }
            __syncthreads();
        }
#pragma unroll
        for (int j = 0; j < 8; j++) kv[dd][e0 + j] = acc[j];
        __syncthreads();
    }

    // ---- step 6: out[l,e] = (q[l,:] . kv[:,e]) * nr[l] * nrr[l] ----
    {
        const int ssg = tid >> 4, ccg = (tid & 15) << 2;
        const int lq = tid >> 5, eq = tid & 31;
        for (int s0 = 0; s0 < LL; s0 += 32) {
            *(float4*)&kt[ssg][ccg] = *(const float4*)(q + base + (size_t)(s0 + ssg) * DM + ccg);
            __syncthreads();
            const int l0 = lq * 2;
            float a00 = 0.f, a01 = 0.f, a10 = 0.f, a11 = 0.f;
#pragma unroll
            for (int d = 0; d < 64; d += 4) {
                float4 qa = *(const float4*)&kt[l0][d];
                float4 qb = *(const float4*)&kt[l0 + 1][d];
                float k0a = kv[d][eq],     k0b = kv[d][eq + 32];
                float k1a = kv[d + 1][eq], k1b = kv[d + 1][eq + 32];
                float k2a = kv[d + 2][eq], k2b = kv[d + 2][eq + 32];
                float k3a = kv[d + 3][eq], k3b = kv[d + 3][eq + 32];
                a00 = fmaf(qa.x, k0a, a00); a00 = fmaf(qa.y, k1a, a00);
                a00 = fmaf(qa.z, k2a, a00); a00 = fmaf(qa.w, k3a, a00);
                a01 = fmaf(qa.x, k0b, a01); a01 = fmaf(qa.y, k1b, a01);
                a01 = fmaf(qa.z, k2b, a01); a01 = fmaf(qa.w, k3b, a01);
                a10 = fmaf(qb.x, k0a, a10); a10 = fmaf(qb.y, k1a, a10);
                a10 = fmaf(qb.z, k2a, a10); a10 = fmaf(qb.w, k3a, a10);
                a11 = fmaf(qb.x, k0b, a11); a11 = fmaf(qb.y, k1b, a11);
                a11 = fmaf(qb.z, k2b, a11); a11 = fmaf(qb.w, k3b, a11);
            }
            const int gl0 = s0 + l0;
            float f0 = nr[bh*LL + gl0] * nrr[bh*LL + gl0];
            float f1 = nr[bh*LL + gl0 + 1] * nrr[bh*LL + gl0 + 1];
            out[base + (size_t)gl0 * DM + eq]            = a00 * f0;
            out[base + (size_t)gl0 * DM + eq + 32]       = a01 * f0;
            out[base + (size_t)(gl0 + 1) * DM + eq]      = a10 * f1;
            out[base + (size_t)(gl0 + 1) * DM + eq + 32] = a11 * f1;
            __syncthreads();
        }
    }
}

// ---------------- channel attention ----------------
__global__ __launch_bounds__(1024) void ca_partial(const float* __restrict__ x, float* __restrict__ part)
{
    int b = blockIdx.x, chk = blockIdx.y, c = threadIdx.x;
    float s = 0.f;
    int l0 = chk * 128;
    for (int l = l0; l < l0 + 128; l++) s += x[((size_t)b * LL + l) * DM + c];
    part[((size_t)b * 16 + chk) * DM + c] = s;
}

__global__ __launch_bounds__(1024) void ca_gate(const float* __restrict__ part,
                                                const float* __restrict__ caw,
                                                float* __restrict__ gate)
{
    __shared__ float m[DM + 4];
    int b = blockIdx.x, c = threadIdx.x;
    float s = 0.f;
    for (int p = 0; p < 16; p++) s += part[((size_t)b * 16 + p) * DM + c];
    m[c + 2] = s * (1.f / (float)LL);
    if (c < 2) m[c] = 0.f;
    if (c >= DM - 2) m[c + 4] = 0.f;
    __syncthreads();
    float g = 0.f;
#pragma unroll
    for (int kk = 0; kk < 5; kk++) g += caw[kk] * m[c + kk];
    gate[(size_t)b * DM + c] = 1.f / (1.f + expf(-g));
}

__global__ __launch_bounds__(1024) void ca_mul(float* __restrict__ x, const float* __restrict__ gate)
{
    int mrow = blockIdx.x;
    int b = mrow / LL;
    int c = threadIdx.x;
    x[(size_t)mrow * DM + c] *= gate[(size_t)b * DM + c];
}

// ---------------- final projection ----------------
__global__ __launch_bounds__(64) void proj_kernel(const float* __restrict__ hln,
                                                  const float* __restrict__ pw,
                                                  const float* __restrict__ pb,
                                                  float* __restrict__ out)
{
    int m = blockIdx.x, n = threadIdx.x;
    const float* hr = hln + (size_t)m * DM;
    const float* wr = pw + (size_t)n * DM;
    float a = 0.f;
    const float4* h4 = (const float4*)hr;
    const float4* w4 = (const float4*)wr;
#pragma unroll 4
    for (int kk = 0; kk < DM/4; kk++) {
        float4 hv = h4[kk], wv = w4[kk];
        a += hv.x*wv.x + hv.y*wv.y + hv.z*wv.z + hv.w*wv.w;
    }
    out[(size_t)m * COUTN + n] = a + pb[n];
}

// ---------------- host ----------------
static inline void cvt_launch(const float* src, float* dst, int n)
{
    int nt = n / 4;
    cvt_rna_kernel<<<(nt + 255) / 256, 256>>>(src, dst, n);
}

extern "C" void kernel_launch(void* const* d_in, const int* in_sizes, int n_in,
                              void* d_out, int out_size)
{
    const float* x    = (const float*)d_in[0];
    const float* tokw = (const float*)d_in[1];
    const float* Wq   = (const float*)d_in[2];
    const float* bq   = (const float*)d_in[3];
    const float* Wk   = (const float*)d_in[4];
    const float* bk   = (const float*)d_in[5];
    const float* Wv   = (const float*)d_in[6];
    const float* bv   = (const float*)d_in[7];
    const float* Wo   = (const float*)d_in[8];
    const float* bo   = (const float*)d_in[9];
    const float* c1w  = (const float*)d_in[10];
    const float* c1b  = (const float*)d_in[11];
    const float* c2w  = (const float*)d_in[12];
    const float* c2b  = (const float*)d_in[13];
    const float* ln1w = (const float*)d_in[14];
    const float* ln1b = (const float*)d_in[15];
    const float* ln2w = (const float*)d_in[16];
    const float* ln2b = (const float*)d_in[17];
    const float* caw  = (const float*)d_in[18];
    const float* lnfw = (const float*)d_in[19];
    const float* lnfb = (const float*)d_in[20];
    const float* pw   = (const float*)d_in[21];
    const float* pb   = (const float*)d_in[22];

    float *p_in192, *p_h, *p_h2, *p_q, *p_k, *p_v, *p_a, *p_t;
    float *p_nr, *p_nc, *p_nrr, *p_sw, *p_part, *p_gate, *p_wc;
    cudaGetSymbolAddress((void**)&p_in192, g_in192);
    cudaGetSymbolAddress((void**)&p_h,  g_h);
    cudaGetSymbolAddress((void**)&p_h2, g_h2);
    cudaGetSymbolAddress((void**)&p_q,  g_q);
    cudaGetSymbolAddress((void**)&p_k,  g_k);
    cudaGetSymbolAddress((void**)&p_v,  g_v);
    cudaGetSymbolAddress((void**)&p_a,  g_a);
    cudaGetSymbolAddress((void**)&p_t,  g_t);
    cudaGetSymbolAddress((void**)&p_nr,  g_nr);
    cudaGetSymbolAddress((void**)&p_nc,  g_nc);
    cudaGetSymbolAddress((void**)&p_nrr, g_nrr);
    cudaGetSymbolAddress((void**)&p_sw,  g_sw);
    cudaGetSymbolAddress((void**)&p_part, g_part);
    cudaGetSymbolAddress((void**)&p_gate, g_gate);
    cudaGetSymbolAddress((void**)&p_wc,  g_wc);

    cudaFuncSetAttribute(gemm_tc, cudaFuncAttributeMaxDynamicSharedMemorySize, GT_SMEM);

    // pre-round all GEMM weights to tf32 (RNA)
    cvt_launch(tokw, p_wc + OFF_TOK, SZ_TOK);
    cvt_launch(Wq,   p_wc + OFF_WQ,  SZ_QKVO);
    cvt_launch(Wk,   p_wc + OFF_WK,  SZ_QKVO);
    cvt_launch(Wv,   p_wc + OFF_WV,  SZ_QKVO);
    cvt_launch(Wo,   p_wc + OFF_WO,  SZ_QKVO);
    cvt_launch(c1w,  p_wc + OFF_C1,  SZ_C);
    cvt_launch(c2w,  p_wc + OFF_C2,  SZ_C);

    const int GRID = 296;   // 2 persistent CTAs per SM (148 SMs)

    // token embedding (circular conv k=3) as gather + GEMM (K=192)
    gather192<<<MM, 192>>>(x, p_in192);
    gemm_tc<<<GRID, 256, GT_SMEM>>>(p_in192, p_wc + OFF_TOK, nullptr, nullptr,
                                    p_h, MM, DM, 192, ACT_NONE);

    for (int rep = 0; rep < 5; rep++) {
        int i = (rep < 4) ? rep : 3;
        const float* wq = p_wc + OFF_WQ + (size_t)i * 1048576;
        const float* wk = p_wc + OFF_WK + (size_t)i * 1048576;
        const float* wv = p_wc + OFF_WV + (size_t)i * 1048576;
        const float* wo = p_wc + OFF_WO + (size_t)i * 1048576;
        const float* w1 = p_wc + OFF_C1 + (size_t)i * (FF * DM);
        const float* w2 = p_wc + OFF_C2 + (size_t)i * (FF * DM);

        gemm_tc<<<GRID, 256, GT_SMEM>>>(p_h, wq, bq + i*DM, nullptr, p_q, MM, DM, DM, ACT_SIG);
        gemm_tc<<<GRID, 256, GT_SMEM>>>(p_h, wk, bk + i*DM, nullptr, p_k, MM, DM, DM, ACT_SIG);
        gemm_tc<<<GRID, 256, GT_SMEM>>>(p_h, wv, bv + i*DM, nullptr, p_v, MM, DM, DM, ACT_NONE);

        flow_attn<<<BB*NH, 512>>>(p_q, p_k, p_v, p_a, p_nr, p_nc, p_nrr, p_sw);

        gemm_tc<<<GRID, 256, GT_SMEM>>>(p_a, wo, bo + i*DM, p_h, p_q, MM, DM, DM, ACT_NONE);
        ln_kernel<<<MM, 256>>>(p_q, ln1w + i*DM, ln1b + i*DM, p_h2);

        gemm_tc<<<GRID, 256, GT_SMEM>>>(p_h2, w1, c1b + i*FF, nullptr, p_t, MM, FF, DM, ACT_RELU);
        gemm_tc<<<GRID, 256, GT_SMEM>>>(p_t, w2, c2b + i*DM, p_h2, p_q, MM, DM, FF, ACT_NONE);
        ln_kernel<<<MM, 256>>>(p_q, ln2w + i*DM, ln2b + i*DM, p_h);

        if (rep < 4) {
            ca_partial<<<dim3(BB, 16), 1024>>>(p_h, p_part);
            ca_gate<<<BB, 1024>>>(p_part, caw + i*5, p_gate);
            ca_mul<<<MM, 1024>>>(p_h, p_gate);
        }
    }

    ln_kernel<<<MM, 256>>>(p_h, lnfw, lnfb, p_h2);
    proj_kernel<<<MM, 64>>>(p_h2, pw, pb, (float*)d_out);
}

// round 7
// speedup vs baseline: 3.0145x; 1.1539x over previous
#include <cuda_runtime.h>
#include <math.h>
#include <stdint.h>

#define BB 4
#define LL 2048
#define CIN 64
#define COUTN 64
#define DM 1024
#define NH 16
#define DH 64
#define FF 4096
#define MM (BB*LL)

#define ACT_NONE 0
#define ACT_RELU 1
#define ACT_SIG  2

// ---------------- scratch (device globals; no cudaMalloc allowed) ----------------
__device__ float g_in192[(size_t)MM*192];
__device__ float g_h [(size_t)MM*DM];
__device__ float g_h2[(size_t)MM*DM];
__device__ float g_q [(size_t)MM*DM];
__device__ float g_k [(size_t)MM*DM];
__device__ float g_v [(size_t)MM*DM];
__device__ float g_a [(size_t)MM*DM];
__device__ float g_t [(size_t)MM*FF];
__device__ float g_nr [BB*NH*LL];
__device__ float g_nc [BB*NH*LL];
__device__ float g_nrr[BB*NH*LL];
__device__ float g_sw [BB*NH*LL];
__device__ float g_part[BB*16*DM];
__device__ float g_gate[BB*DM];

// pre-rounded (tf32 RNA) weights
#define OFF_TOK 0
#define SZ_TOK  196608
#define OFF_WQ  196608
#define SZ_QKVO 4194304
#define OFF_WK  4390912
#define OFF_WV  8585216
#define OFF_WO  12779520
#define OFF_C1  16973824
#define SZ_C    16777216
#define OFF_C2  33751040
#define WC_TOTAL 50528256
__device__ float g_wc[(size_t)WC_TOTAL];

// ---------------- helpers ----------------
__device__ __forceinline__ uint32_t smem_u32(const void* p) {
    uint32_t addr;
    asm("{ .reg .u64 tmp; cvta.to.shared.u64 tmp, %1; cvt.u32.u64 %0, tmp; }"
        : "=r"(addr) : "l"(p));
    return addr;
}

__device__ __forceinline__ float to_tf32(float x) {
    float r;
    asm("cvt.rna.tf32.f32 %0, %1;" : "=f"(r) : "f"(x));
    return r;
}

__device__ __forceinline__ void mma_tf32(float* d, const unsigned* a, const unsigned* b) {
    asm volatile(
        "mma.sync.aligned.m16n8k8.row.col.f32.tf32.tf32.f32 "
        "{%0,%1,%2,%3}, {%4,%5,%6,%7}, {%8,%9}, {%0,%1,%2,%3};"
        : "+f"(d[0]), "+f"(d[1]), "+f"(d[2]), "+f"(d[3])
        : "r"(a[0]), "r"(a[1]), "r"(a[2]), "r"(a[3]), "r"(b[0]), "r"(b[1]));
}

#define LDSM4(r0, r1, r2, r3, addr) \
    asm volatile("ldmatrix.sync.aligned.m8n8.x4.shared.b16 {%0,%1,%2,%3}, [%4];" \
                 : "=r"(r0), "=r"(r1), "=r"(r2), "=r"(r3) : "r"(addr))

#define CP16(dst_u32, src_ptr) \
    asm volatile("cp.async.cg.shared.global [%0], [%1], 16;" \
                 :: "r"(dst_u32), "l"(src_ptr) : "memory")
#define CP_COMMIT() asm volatile("cp.async.commit_group;" ::: "memory")
#define CP_WAIT(n)  asm volatile("cp.async.wait_group %0;" :: "n"(n) : "memory")

// ---------------- fused weight pre-round (single launch) ----------------
struct CvtArgs {
    const float* src[7];
    long off[7];
    long n[7];
};

__global__ __launch_bounds__(256) void cvt_all_kernel(CvtArgs a, float* __restrict__ dst)
{
    long i = ((long)blockIdx.x * blockDim.x + threadIdx.x) * 4;
#pragma unroll
    for (int s = 0; s < 7; s++) {
        if (i < a.n[s]) {
            float4 v = *(const float4*)(a.src[s] + i);
            v.x = to_tf32(v.x); v.y = to_tf32(v.y);
            v.z = to_tf32(v.z); v.w = to_tf32(v.w);
            *(float4*)(dst + a.off[s] + i) = v;
            return;
        }
        i -= a.n[s];
    }
}

// ---------------- tf32 mma.sync GEMM: C[m,n] = sum_k A[m,k]*W[n,k] (+bias)(+res)(act)
// persistent CTAs, 256 threads (8 warps 2x4, warp tile 64x32), tile 128x128x32,
// both operands cp.async (inputs pre-rounded tf32/RNA at producers),
// ldmatrix.x4 fragment loads.
#define SSTR 36
#define GT_SMEM (4*128*SSTR*4)   // 73728 bytes

__global__ __launch_bounds__(256, 2) void gemm_tc(
    const float* __restrict__ A, const float* __restrict__ W,
    const float* __restrict__ bias, const float* __restrict__ res,
    float* __restrict__ C, int Mm, int Nn, int Kk, int act, int rnd)
{
    extern __shared__ float smem[];
    uint32_t uA[2], uB[2];
    uA[0] = smem_u32(smem);
    uA[1] = uA[0] + 128*SSTR*4;
    uB[0] = uA[0] + 2*128*SSTR*4;
    uB[1] = uA[0] + 3*128*SSTR*4;

    const int tid = threadIdx.x;
    const int warp = tid >> 5, lane = tid & 31;
    const int gid = lane >> 2, tig = lane & 3;
    const int wm = (warp & 1) * 64;      // 2 warps across m
    const int wn = (warp >> 1) * 32;     // 4 warps across n

    // per-lane ldmatrix base offsets (in floats)
    const int j8  = lane & 7;
    const int sel = lane >> 3;           // 0..3
    // A x4: m0=rows wm+mi*16+j8 colq k8 ; m1=rows +8 ; m2=rows colq k8+4 ; m3=rows+8 colq k8+4
    const int aoff = (wm + (sel & 1) * 8 + j8) * SSTR + ((sel >> 1) ? 4 : 0);
    // B x4 pair pn: m0=rows wn+pn*8+j8 k-lo ; m1 same rows k-hi ; m2 rows +8 k-lo ; m3 rows+8 k-hi
    const int boff = (wn + (sel >> 1) * 8 + j8) * SSTR + ((sel & 1) ? 4 : 0);

    const int ntn = Nn / 128;
    const int ntiles = (Mm / 128) * ntn;
    const int T = Kk / 32;

    int rowi[4], qi[4];
#pragma unroll
    for (int j = 0; j < 4; j++) {
        int idx = tid + j * 256;
        rowi[j] = idx >> 3;
        qi[j] = idx & 7;
    }

    for (int tile = blockIdx.x; tile < ntiles; tile += gridDim.x) {
        const int bm = (tile / ntn) * 128;
        const int bn = (tile % ntn) * 128;

        float acc[4][4][4];
#pragma unroll
        for (int mi = 0; mi < 4; mi++)
#pragma unroll
            for (int ni = 0; ni < 4; ni++)
#pragma unroll
                for (int r = 0; r < 4; r++) acc[mi][ni][r] = 0.f;

        // prologue: k-tile 0 -> buf 0
#pragma unroll
        for (int j = 0; j < 4; j++) {
            uint32_t d = (uint32_t)(rowi[j] * SSTR + qi[j] * 4) * 4;
            CP16(uA[0] + d, A + (size_t)(bm + rowi[j]) * Kk + qi[j] * 4);
            CP16(uB[0] + d, W + (size_t)(bn + rowi[j]) * Kk + qi[j] * 4);
        }
        CP_COMMIT();

        for (int t = 0; t < T; t++) {
            const int buf = t & 1;
            if (t + 1 < T) {
                const int k0 = (t + 1) * 32;
                const int nb = (t + 1) & 1;
#pragma unroll
                for (int j = 0; j < 4; j++) {
                    uint32_t d = (uint32_t)(rowi[j] * SSTR + qi[j] * 4) * 4;
                    CP16(uA[nb] + d, A + (size_t)(bm + rowi[j]) * Kk + k0 + qi[j] * 4);
                    CP16(uB[nb] + d, W + (size_t)(bn + rowi[j]) * Kk + k0 + qi[j] * 4);
                }
                CP_COMMIT();
                CP_WAIT(1);
            } else {
                CP_WAIT(0);
            }
            __syncthreads();

            const uint32_t abase = uA[buf] + (uint32_t)aoff * 4;
            const uint32_t bbase = uB[buf] + (uint32_t)boff * 4;
#pragma unroll
            for (int k8 = 0; k8 < 32; k8 += 8) {
                unsigned af[4][4], bf[4][2];
#pragma unroll
                for (int mi = 0; mi < 4; mi++)
                    LDSM4(af[mi][0], af[mi][1], af[mi][2], af[mi][3],
                          abase + (uint32_t)(mi * 16 * SSTR + k8) * 4);
                // B pairs: pn=0 -> bf[0],bf[1] ; pn=2 -> bf[2],bf[3]
                LDSM4(bf[0][0], bf[0][1], bf[1][0], bf[1][1],
                      bbase + (uint32_t)k8 * 4);
                LDSM4(bf[2][0], bf[2][1], bf[3][0], bf[3][1],
                      bbase + (uint32_t)(16 * SSTR + k8) * 4);
#pragma unroll
                for (int mi = 0; mi < 4; mi++)
#pragma unroll
                    for (int ni = 0; ni < 4; ni++)
                        mma_tf32(acc[mi][ni], af[mi], bf[ni]);
            }
            __syncthreads();
        }

        // epilogue
#pragma unroll
        for (int mi = 0; mi < 4; mi++) {
            int row = bm + wm + mi * 16 + gid;
#pragma unroll
            for (int ni = 0; ni < 4; ni++) {
                int col = bn + wn + ni * 8 + 2 * tig;
                float b0 = 0.f, b1 = 0.f;
                if (bias) { b0 = bias[col]; b1 = bias[col + 1]; }
#pragma unroll
                for (int half = 0; half < 2; half++) {
                    int r = row + half * 8;
                    float v0 = acc[mi][ni][half * 2 + 0] + b0;
                    float v1 = acc[mi][ni][half * 2 + 1] + b1;
                    if (res) {
                        v0 += res[(size_t)r * Nn + col];
                        v1 += res[(size_t)r * Nn + col + 1];
                    }
                    if (act == ACT_RELU) { v0 = fmaxf(v0, 0.f); v1 = fmaxf(v1, 0.f); }
                    else if (act == ACT_SIG) {
                        v0 = 1.f / (1.f + expf(-v0));
                        v1 = 1.f / (1.f + expf(-v1));
                    }
                    if (rnd) { v0 = to_tf32(v0); v1 = to_tf32(v1); }
                    *(float2*)(C + (size_t)r * Nn + col) = make_float2(v0, v1);
                }
            }
        }
    }
}

// ---------------- token embed gather (rounded: feeds tokemb GEMM A) ----------------
__global__ void gather192(const float* __restrict__ x, float* __restrict__ a)
{
    int m = blockIdx.x;
    int b = m / LL, l = m % LL;
    int t = threadIdx.x;          // 0..191
    int c = t / 3, kk = t % 3;
    int ll = l + kk - 1;
    ll = (ll + LL) % LL;
    a[(size_t)m * 192 + t] = to_tf32(x[((size_t)b * LL + ll) * CIN + c]);
}

// ---------------- layer norm (1024); rnd=1 rounds output to tf32 ----------------
__global__ __launch_bounds__(256) void ln_kernel(
    const float* __restrict__ x, const float* __restrict__ w,
    const float* __restrict__ b, float* __restrict__ out, int rnd)
{
    __shared__ float s1[8], s2[8];
    const int m = blockIdx.x, tid = threadIdx.x;
    const int wid = tid >> 5, lane = tid & 31;
    const float* row = x + (size_t)m * DM;

    float4 v = *(const float4*)(row + tid * 4);
    float s = v.x + v.y + v.z + v.w;
#pragma unroll
    for (int o = 16; o >= 1; o >>= 1) s += __shfl_xor_sync(0xFFFFFFFFu, s, o);
    if (lane == 0) s1[wid] = s;
    __syncthreads();
    float tot = s1[0] + s1[1] + s1[2] + s1[3] + s1[4] + s1[5] + s1[6] + s1[7];
    const float mean = tot * (1.f / 1024.f);

    float dx = v.x - mean, dy = v.y - mean, dz = v.z - mean, dw = v.w - mean;
    float q = dx * dx + dy * dy + dz * dz + dw * dw;
#pragma unroll
    for (int o = 16; o >= 1; o >>= 1) q += __shfl_xor_sync(0xFFFFFFFFu, q, o);
    if (lane == 0) s2[wid] = q;
    __syncthreads();
    float qt = s2[0] + s2[1] + s2[2] + s2[3] + s2[4] + s2[5] + s2[6] + s2[7];
    const float inv = rsqrtf(qt * (1.f / 1024.f) + 1e-5f);

    float4 wv = *(const float4*)(w + tid * 4);
    float4 bv = *(const float4*)(b + tid * 4);
    float4 o4;
    o4.x = dx * inv * wv.x + bv.x;
    o4.y = dy * inv * wv.y + bv.y;
    o4.z = dz * inv * wv.z + bv.z;
    o4.w = dw * inv * wv.w + bv.w;
    if (rnd) {
        o4.x = to_tf32(o4.x); o4.y = to_tf32(o4.y);
        o4.z = to_tf32(o4.z); o4.w = to_tf32(o4.w);
    }
    *(float4*)(out + (size_t)m * DM + tid * 4) = o4;
}

// ---------------- flow attention: one block per (b,h); output rounded ----------------
__global__ __launch_bounds__(512) void flow_attn(
    const float* __restrict__ q, const float* __restrict__ k,
    const float* __restrict__ v, float* __restrict__ out,
    float* __restrict__ nr, float* __restrict__ nc,
    float* __restrict__ nrr, float* __restrict__ sw)
{
    const int bh = blockIdx.x;
    const int b = bh / NH, h = bh % NH;
    const size_t base = ((size_t)b * LL) * DM + (size_t)h * DH;
    const int tid = threadIdx.x;
    const float eps = 1e-6f;

    __shared__ float ksum[64], qsum[64], skn[64], sqn[64];
    __shared__ float red[512];
    __shared__ float kv[64][64];
    __shared__ float kt[32][64], vt[32][64], wt[32];

    const int d8 = tid & 63, ch = tid >> 6;

    // ---- step 1: ksum, qsum ----
    {
        float aq = 0.f, ak = 0.f;
        for (int l = ch; l < LL; l += 8) {
            size_t off = base + (size_t)l * DM + d8;
            aq += q[off]; ak += k[off];
        }
        red[tid] = aq; __syncthreads();
        for (int s = 4; s >= 1; s >>= 1) { if (ch < s) red[tid] += red[tid + (s<<6)]; __syncthreads(); }
        if (tid < 64) qsum[tid] = red[tid];
        __syncthreads();
        red[tid] = ak; __syncthreads();
        for (int s = 4; s >= 1; s >>= 1) { if (ch < s) red[tid] += red[tid + (s<<6)]; __syncthreads(); }
        if (tid < 64) ksum[tid] = red[tid];
        __syncthreads();
    }

    // ---- step 2: nr[l], nc[s] ----
    for (int l = tid; l < LL; l += 512) {
        const float4* q4 = (const float4*)(q + base + (size_t)l * DM);
        const float4* k4 = (const float4*)(k + base + (size_t)l * DM);
        float dq = 0.f, dk = 0.f;
#pragma unroll
        for (int d = 0; d < 16; d++) {
            float4 qv = q4[d], kvv = k4[d];
            float4 ks4 = *(const float4*)&ksum[d * 4];
            float4 qs4 = *(const float4*)&qsum[d * 4];
            dq += (qv.x + eps) * (ks4.x + eps) + (qv.y + eps) * (ks4.y + eps)
                + (qv.z + eps) * (ks4.z + eps) + (qv.w + eps) * (ks4.w + eps);
            dk += (kvv.x + eps) * (qs4.x + eps) + (kvv.y + eps) * (qs4.y + eps)
                + (kvv.z + eps) * (qs4.z + eps) + (kvv.w + eps) * (qs4.w + eps);
        }
        nr[bh*LL + l] = 1.f / dq;
        nc[bh*LL + l] = 1.f / dk;
    }
    __syncthreads();

    // ---- step 3: skn = sum_s k*nc ; sqn = sum_l q*nr ----
    {
        float a1 = 0.f, a2 = 0.f;
        for (int l = ch; l < LL; l += 8) {
            size_t off = base + (size_t)l * DM + d8;
            a1 += k[off] * nc[bh*LL + l];
            a2 += q[off] * nr[bh*LL + l];
        }
        red[tid] = a1; __syncthreads();
        for (int s = 4; s >= 1; s >>= 1) { if (ch < s) red[tid] += red[tid + (s<<6)]; __syncthreads(); }
        if (tid < 64) skn[tid] = red[tid];
        __syncthreads();
        red[tid] = a2; __syncthreads();
        for (int s = 4; s >= 1; s >>= 1) { if (ch < s) red[tid] += red[tid + (s<<6)]; __syncthreads(); }
        if (tid < 64) sqn[tid] = red[tid];
        __syncthreads();
    }

    // ---- step 4: ncr (softmax*L), nrr ----
    float lmax = -1e30f;
    for (int l = tid; l < LL; l += 512) {
        const float4* k4 = (const float4*)(k + base + (size_t)l * DM);
        const float4* q4 = (const float4*)(q + base + (size_t)l * DM);
        float dc = 0.f, dr = 0.f;
#pragma unroll
        for (int d = 0; d < 16; d++) {
            float4 kvv = k4[d], qv = q4[d];
            float4 sq4 = *(const float4*)&sqn[d * 4];
            float4 sk4 = *(const float4*)&skn[d * 4];
            dc += (kvv.x + eps) * (sq4.x + eps) + (kvv.y + eps) * (sq4.y + eps)
                + (kvv.z + eps) * (sq4.z + eps) + (kvv.w + eps) * (sq4.w + eps);
            dr += (qv.x + eps) * (sk4.x + eps) + (qv.y + eps) * (sk4.y + eps)
                + (qv.z + eps) * (sk4.z + eps) + (qv.w + eps) * (sk4.w + eps);
        }
        sw[bh*LL + l] = dc;
        nrr[bh*LL + l] = 1.f / (1.f + expf(-dr));
        lmax = fmaxf(lmax, dc);
    }
    red[tid] = lmax; __syncthreads();
    for (int s = 256; s >= 1; s >>= 1) { if (tid < s) red[tid] = fmaxf(red[tid], red[tid + s]); __syncthreads(); }
    float mx = red[0];
    __syncthreads();
    float lsum = 0.f;
    for (int l = tid; l < LL; l += 512) {
        float e = expf(sw[bh*LL + l] - mx);
        sw[bh*LL + l] = e;
        lsum += e;
    }
    red[tid] = lsum; __syncthreads();
    for (int s = 256; s >= 1; s >>= 1) { if (tid < s) red[tid] += red[tid + s]; __syncthreads(); }
    const float wfac = (float)LL / red[0];
    __syncthreads();

    // ---- step 5: kv[d][e] = sum_s k[s,d] * (v[s,e] * w[s]) ----
    {
        float acc[8];
#pragma unroll
        for (int j = 0; j < 8; j++) acc[j] = 0.f;
        const int dd = tid >> 3, e0 = (tid & 7) << 3;
        const int ssg = tid >> 4, ccg = (tid & 15) << 2;
        for (int s0 = 0; s0 < LL; s0 += 32) {
            *(float4*)&kt[ssg][ccg] = *(const float4*)(k + base + (size_t)(s0 + ssg) * DM + ccg);
            *(float4*)&vt[ssg][ccg] = *(const float4*)(v + base + (size_t)(s0 + ssg) * DM + ccg);
            if (tid < 32) wt[tid] = sw[bh*LL + s0 + tid] * wfac;
            __syncthreads();
#pragma unroll 8
            for (int ss = 0; ss < 32; ss++) {
                float kw = kt[ss][dd] * wt[ss];
                float4 va = *(const float4*)&vt[ss][e0];
                float4 vb = *(const float4*)&vt[ss][e0 + 4];
                acc[0] = fmaf(kw, va.x, acc[0]); acc[1] = fmaf(kw, va.y, acc[1]);
                acc[2] = fmaf(kw, va.z, acc[2]); acc[3] = fmaf(kw, va.w, acc[3]);
                acc[4] = fmaf(kw, vb.x, acc[4]); acc[5] = fmaf(kw, vb.y, acc[5]);
                acc[6] = fmaf(kw, vb.z, acc[6]); acc[7] = fmaf(kw, vb.w, acc[7]);
            }
            __syncthreads();
        }
#pragma unroll
        for (int j = 0; j < 8; j++) kv[dd][e0 + j] = acc[j];
        __syncthreads();
    }

    // ---- step 6: out[l,e] = (q[l,:] . kv[:,e]) * nr[l] * nrr[l] (rounded) ----
    {
        const int ssg = tid >> 4, ccg = (tid & 15) << 2;
        const int lq = tid >> 5, eq = tid & 31;
        for (int s0 = 0; s0 < LL; s0 += 32) {
            *(float4*)&kt[ssg][ccg] = *(const float4*)(q + base + (size_t)(s0 + ssg) * DM + ccg);
            __syncthreads();
            const int l0 = lq * 2;
            float a00 = 0.f, a01 = 0.f, a10 = 0.f, a11 = 0.f;
#pragma unroll
            for (int d = 0; d < 64; d += 4) {
                float4 qa = *(const float4*)&kt[l0][d];
                float4 qb = *(const float4*)&kt[l0 + 1][d];
                float k0a = kv[d][eq],     k0b = kv[d][eq + 32];
                float k1a = kv[d + 1][eq], k1b = kv[d + 1][eq + 32];
                float k2a = kv[d + 2][eq], k2b = kv[d + 2][eq + 32];
                float k3a = kv[d + 3][eq], k3b = kv[d + 3][eq + 32];
                a00 = fmaf(qa.x, k0a, a00); a00 = fmaf(qa.y, k1a, a00);
                a00 = fmaf(qa.z, k2a, a00); a00 = fmaf(qa.w, k3a, a00);
                a01 = fmaf(qa.x, k0b, a01); a01 = fmaf(qa.y, k1b, a01);
                a01 = fmaf(qa.z, k2b, a01); a01 = fmaf(qa.w, k3b, a01);
                a10 = fmaf(qb.x, k0a, a10); a10 = fmaf(qb.y, k1a, a10);
                a10 = fmaf(qb.z, k2a, a10); a10 = fmaf(qb.w, k3a, a10);
                a11 = fmaf(qb.x, k0b, a11); a11 = fmaf(qb.y, k1b, a11);
                a11 = fmaf(qb.z, k2b, a11); a11 = fmaf(qb.w, k3b, a11);
            }
            const int gl0 = s0 + l0;
            float f0 = nr[bh*LL + gl0] * nrr[bh*LL + gl0];
            float f1 = nr[bh*LL + gl0 + 1] * nrr[bh*LL + gl0 + 1];
            out[base + (size_t)gl0 * DM + eq]            = to_tf32(a00 * f0);
            out[base + (size_t)gl0 * DM + eq + 32]       = to_tf32(a01 * f0);
            out[base + (size_t)(gl0 + 1) * DM + eq]      = to_tf32(a10 * f1);
            out[base + (size_t)(gl0 + 1) * DM + eq + 32] = to_tf32(a11 * f1);
            __syncthreads();
        }
    }
}

// ---------------- channel attention ----------------
__global__ __launch_bounds__(1024) void ca_partial(const float* __restrict__ x, float* __restrict__ part)
{
    int b = blockIdx.x, chk = blockIdx.y, c = threadIdx.x;
    float s = 0.f;
    int l0 = chk * 128;
    for (int l = l0; l < l0 + 128; l++) s += x[((size_t)b * LL + l) * DM + c];
    part[((size_t)b * 16 + chk) * DM + c] = s;
}

__global__ __launch_bounds__(1024) void ca_gate(const float* __restrict__ part,
                                                const float* __restrict__ caw,
                                                float* __restrict__ gate)
{
    __shared__ float m[DM + 4];
    int b = blockIdx.x, c = threadIdx.x;
    float s = 0.f;
    for (int p = 0; p < 16; p++) s += part[((size_t)b * 16 + p) * DM + c];
    m[c + 2] = s * (1.f / (float)LL);
    if (c < 2) m[c] = 0.f;
    if (c >= DM - 2) m[c + 4] = 0.f;
    __syncthreads();
    float g = 0.f;
#pragma unroll
    for (int kk = 0; kk < 5; kk++) g += caw[kk] * m[c + kk];
    gate[(size_t)b * DM + c] = 1.f / (1.f + expf(-g));
}

// output rounded: feeds next layer's Q/K/V GEMMs
__global__ __launch_bounds__(1024) void ca_mul(float* __restrict__ x, const float* __restrict__ gate)
{
    int mrow = blockIdx.x;
    int b = mrow / LL;
    int c = threadIdx.x;
    x[(size_t)mrow * DM + c] = to_tf32(x[(size_t)mrow * DM + c] * gate[(size_t)b * DM + c]);
}

// ---------------- final projection ----------------
__global__ __launch_bounds__(64) void proj_kernel(const float* __restrict__ hln,
                                                  const float* __restrict__ pw,
                                                  const float* __restrict__ pb,
                                                  float* __restrict__ out)
{
    int m = blockIdx.x, n = threadIdx.x;
    const float* hr = hln + (size_t)m * DM;
    const float* wr = pw + (size_t)n * DM;
    float a = 0.f;
    const float4* h4 = (const float4*)hr;
    const float4* w4 = (const float4*)wr;
#pragma unroll 4
    for (int kk = 0; kk < DM/4; kk++) {
        float4 hv = h4[kk], wv = w4[kk];
        a += hv.x*wv.x + hv.y*wv.y + hv.z*wv.z + hv.w*wv.w;
    }
    out[(size_t)m * COUTN + n] = a + pb[n];
}

// ---------------- host ----------------
extern "C" void kernel_launch(void* const* d_in, const int* in_sizes, int n_in,
                              void* d_out, int out_size)
{
    const float* x    = (const float*)d_in[0];
    const float* tokw = (const float*)d_in[1];
    const float* Wq   = (const float*)d_in[2];
    const float* bq   = (const float*)d_in[3];
    const float* Wk   = (const float*)d_in[4];
    const float* bk   = (const float*)d_in[5];
    const float* Wv   = (const float*)d_in[6];
    const float* bv   = (const float*)d_in[7];
    const float* Wo   = (const float*)d_in[8];
    const float* bo   = (const float*)d_in[9];
    const float* c1w  = (const float*)d_in[10];
    const float* c1b  = (const float*)d_in[11];
    const float* c2w  = (const float*)d_in[12];
    const float* c2b  = (const float*)d_in[13];
    const float* ln1w = (const float*)d_in[14];
    const float* ln1b = (const float*)d_in[15];
    const float* ln2w = (const float*)d_in[16];
    const float* ln2b = (const float*)d_in[17];
    const float* caw  = (const float*)d_in[18];
    const float* lnfw = (const float*)d_in[19];
    const float* lnfb = (const float*)d_in[20];
    const float* pw   = (const float*)d_in[21];
    const float* pb   = (const float*)d_in[22];

    float *p_in192, *p_h, *p_h2, *p_q, *p_k, *p_v, *p_a, *p_t;
    float *p_nr, *p_nc, *p_nrr, *p_sw, *p_part, *p_gate, *p_wc;
    cudaGetSymbolAddress((void**)&p_in192, g_in192);
    cudaGetSymbolAddress((void**)&p_h,  g_h);
    cudaGetSymbolAddress((void**)&p_h2, g_h2);
    cudaGetSymbolAddress((void**)&p_q,  g_q);
    cudaGetSymbolAddress((void**)&p_k,  g_k);
    cudaGetSymbolAddress((void**)&p_v,  g_v);
    cudaGetSymbolAddress((void**)&p_a,  g_a);
    cudaGetSymbolAddress((void**)&p_t,  g_t);
    cudaGetSymbolAddress((void**)&p_nr,  g_nr);
    cudaGetSymbolAddress((void**)&p_nc,  g_nc);
    cudaGetSymbolAddress((void**)&p_nrr, g_nrr);
    cudaGetSymbolAddress((void**)&p_sw,  g_sw);
    cudaGetSymbolAddress((void**)&p_part, g_part);
    cudaGetSymbolAddress((void**)&p_gate, g_gate);
    cudaGetSymbolAddress((void**)&p_wc,  g_wc);

    cudaFuncSetAttribute(gemm_tc, cudaFuncAttributeMaxDynamicSharedMemorySize, GT_SMEM);

    // pre-round all GEMM weights to tf32 (RNA) in a single launch
    CvtArgs ca;
    ca.src[0] = tokw; ca.off[0] = OFF_TOK; ca.n[0] = SZ_TOK;
    ca.src[1] = Wq;   ca.off[1] = OFF_WQ;  ca.n[1] = SZ_QKVO;
    ca.src[2] = Wk;   ca.off[2] = OFF_WK;  ca.n[2] = SZ_QKVO;
    ca.src[3] = Wv;   ca.off[3] = OFF_WV;  ca.n[3] = SZ_QKVO;
    ca.src[4] = Wo;   ca.off[4] = OFF_WO;  ca.n[4] = SZ_QKVO;
    ca.src[5] = c1w;  ca.off[5] = OFF_C1;  ca.n[5] = SZ_C;
    ca.src[6] = c2w;  ca.off[6] = OFF_C2;  ca.n[6] = SZ_C;
    cvt_all_kernel<<<(WC_TOTAL/4 + 255) / 256, 256>>>(ca, p_wc);

    const int GRID = 296;   // 2 persistent CTAs per SM (148 SMs)

    gather192<<<MM, 192>>>(x, p_in192);
    gemm_tc<<<GRID, 256, GT_SMEM>>>(p_in192, p_wc + OFF_TOK, nullptr, nullptr,
                                    p_h, MM, DM, 192, ACT_NONE, 1);

    for (int rep = 0; rep < 5; rep++) {
        int i = (rep < 4) ? rep : 3;
        const float* wq = p_wc + OFF_WQ + (size_t)i * 1048576;
        const float* wk = p_wc + OFF_WK + (size_t)i * 1048576;
        const float* wv = p_wc + OFF_WV + (size_t)i * 1048576;
        const float* wo = p_wc + OFF_WO + (size_t)i * 1048576;
        const float* w1 = p_wc + OFF_C1 + (size_t)i * (FF * DM);
        const float* w2 = p_wc + OFF_C2 + (size_t)i * (FF * DM);

        gemm_tc<<<GRID, 256, GT_SMEM>>>(p_h, wq, bq + i*DM, nullptr, p_q, MM, DM, DM, ACT_SIG, 0);
        gemm_tc<<<GRID, 256, GT_SMEM>>>(p_h, wk, bk + i*DM, nullptr, p_k, MM, DM, DM, ACT_SIG, 0);
        gemm_tc<<<GRID, 256, GT_SMEM>>>(p_h, wv, bv + i*DM, nullptr, p_v, MM, DM, DM, ACT_NONE, 0);

        flow_attn<<<BB*NH, 512>>>(p_q, p_k, p_v, p_a, p_nr, p_nc, p_nrr, p_sw);

        gemm_tc<<<GRID, 256, GT_SMEM>>>(p_a, wo, bo + i*DM, p_h, p_q, MM, DM, DM, ACT_NONE, 0);
        ln_kernel<<<MM, 256>>>(p_q, ln1w + i*DM, ln1b + i*DM, p_h2, 1);

        gemm_tc<<<GRID, 256, GT_SMEM>>>(p_h2, w1, c1b + i*FF, nullptr, p_t, MM, FF, DM, ACT_RELU, 1);
        gemm_tc<<<GRID, 256, GT_SMEM>>>(p_t, w2, c2b + i*DM, p_h2, p_q, MM, DM, FF, ACT_NONE, 0);
        ln_kernel<<<MM, 256>>>(p_q, ln2w + i*DM, ln2b + i*DM, p_h, 1);

        if (rep < 4) {
            ca_partial<<<dim3(BB, 16), 1024>>>(p_h, p_part);
            ca_gate<<<BB, 1024>>>(p_part, caw + i*5, p_gate);
            ca_mul<<<MM, 1024>>>(p_h, p_gate);
        }
    }

    ln_kernel<<<MM, 256>>>(p_h, lnfw, lnfb, p_h2, 0);
    proj_kernel<<<MM, 64>>>(p_h2, pw, pb, (float*)d_out);
}